// round 2
// baseline (speedup 1.0000x reference)
#include <cuda_runtime.h>
#include <cuda_bf16.h>
#include <cstdint>
#include <cstddef>

#define Bq 2
#define Lq 4096
#define Dq 2048
#define Hq 16
#define Dh 128
#define Cq 64
#define Nq (Lq / Cq)
#define KW 4
#define BLq (Bq * Lq)
#define EPSq 1e-5f

// ---------------- device scratch buffers (no allocation allowed) ----------------
#define BLD (BLq * Dq)         // 16,777,216
#define BHL (Bq * Hq * Lq)     // 131,072

__device__ float g_projq[BLD];   // x@Wq^T ; reused as gated output (og) later
__device__ float g_projk[BLD];   // x@Wk^T ; reused as scan output (o) later
__device__ float g_projv[BLD];   // x@Wv^T
__device__ float g_projg[BLD];   // x@Wg^T (gate, no conv)
__device__ float g_qn[BLD];      // conv+silu+l2norm q (scaled by 1/sqrt(Dh))
__device__ float g_kn[BLD];      // conv+silu+l2norm k
__device__ float g_vn[BLD];      // conv+silu v
__device__ float g_beta[BHL];
__device__ float g_gdec[BHL];

// ---------------- SGEMM: C[M,N] = A[M,K] * B[N,K]^T  (fp32) ----------------
// 128x128 block tile, BK=8, 256 threads, 8x8 per thread.
__global__ __launch_bounds__(256, 2)
void sgemm_nt(const float* __restrict__ A, const float* __restrict__ Bw,
              float* __restrict__ C, int M, int N, int K)
{
    __shared__ float As[8][132];
    __shared__ float Bs[8][132];

    const int bm = blockIdx.y * 128;
    const int bn = blockIdx.x * 128;
    const int tid = threadIdx.x;
    const int tm = (tid / 16) * 8;
    const int tn = (tid % 16) * 8;

    // global load mapping: 128 rows x 8 cols per tile = 256 float4 loads
    const int lr = tid >> 1;
    const int lc = (tid & 1) * 4;
    const float* Ap = A + (size_t)(bm + lr) * K + lc;
    const float* Bp = Bw + (size_t)(bn + lr) * K + lc;

    float acc[8][8];
#pragma unroll
    for (int i = 0; i < 8; i++)
#pragma unroll
        for (int j = 0; j < 8; j++) acc[i][j] = 0.f;

    for (int k0 = 0; k0 < K; k0 += 8) {
        float4 av = *(const float4*)(Ap + k0);
        float4 bv = *(const float4*)(Bp + k0);
        As[lc + 0][lr] = av.x; As[lc + 1][lr] = av.y;
        As[lc + 2][lr] = av.z; As[lc + 3][lr] = av.w;
        Bs[lc + 0][lr] = bv.x; Bs[lc + 1][lr] = bv.y;
        Bs[lc + 2][lr] = bv.z; Bs[lc + 3][lr] = bv.w;
        __syncthreads();
#pragma unroll
        for (int kk = 0; kk < 8; kk++) {
            float a[8], bb[8];
            *(float4*)(a)      = *(const float4*)&As[kk][tm];
            *(float4*)(a + 4)  = *(const float4*)&As[kk][tm + 4];
            *(float4*)(bb)     = *(const float4*)&Bs[kk][tn];
            *(float4*)(bb + 4) = *(const float4*)&Bs[kk][tn + 4];
#pragma unroll
            for (int i = 0; i < 8; i++)
#pragma unroll
                for (int j = 0; j < 8; j++) acc[i][j] += a[i] * bb[j];
        }
        __syncthreads();
    }
#pragma unroll
    for (int i = 0; i < 8; i++) {
        float* Cr = C + (size_t)(bm + tm + i) * N + bn + tn;
        *(float4*)(Cr)     = make_float4(acc[i][0], acc[i][1], acc[i][2], acc[i][3]);
        *(float4*)(Cr + 4) = make_float4(acc[i][4], acc[i][5], acc[i][6], acc[i][7]);
    }
}

// ---------------- beta / g kernel ----------------
// grid = BL, 512 threads = 16 warps (one per head)
__global__ void betag_kernel(const float* __restrict__ x,
                             const float* __restrict__ Wb,
                             const float* __restrict__ Wa,
                             const float* __restrict__ A_log,
                             const float* __restrict__ dt_bias,
                             float* __restrict__ beta,
                             float* __restrict__ gdec)
{
    const int bl = blockIdx.x;
    const int h = threadIdx.x >> 5;
    const int lane = threadIdx.x & 31;
    const float* xr = x + (size_t)bl * Dq;
    const float* wb = Wb + (size_t)h * Dq;
    const float* wa = Wa + (size_t)h * Dq;
    float sb = 0.f, sa = 0.f;
    for (int i = lane; i < Dq; i += 32) {
        float xv = xr[i];
        sb += xv * wb[i];
        sa += xv * wa[i];
    }
#pragma unroll
    for (int off = 16; off > 0; off >>= 1) {
        sb += __shfl_down_sync(0xffffffffu, sb, off);
        sa += __shfl_down_sync(0xffffffffu, sa, off);
    }
    if (lane == 0) {
        const int b = bl / Lq, l = bl % Lq;
        float bet = 1.f / (1.f + expf(-sb));
        float z = sa + dt_bias[h];
        float sp = (z > 15.f) ? z : log1pf(expf(z));
        float g = -expf(A_log[h]) * sp;
        size_t o = ((size_t)(b * Hq + h)) * Lq + l;
        beta[o] = bet;
        gdec[o] = g;
    }
}

// ---------------- causal dwconv + silu + l2 norm ----------------
// grid = B*L*H, 128 threads (one per d)
__global__ void conv_kernel(const float* __restrict__ pq, const float* __restrict__ pk,
                            const float* __restrict__ pv,
                            const float* __restrict__ wq, const float* __restrict__ wk,
                            const float* __restrict__ wv,
                            float* __restrict__ oq, float* __restrict__ ok,
                            float* __restrict__ ov)
{
    const int blk = blockIdx.x;
    const int h = blk % Hq;
    const int bl = blk / Hq;       // b*L + l
    const int l = bl % Lq;
    const int d = threadIdx.x;
    const int c = h * Dh + d;

    float aq = 0.f, ak = 0.f, av = 0.f;
#pragma unroll
    for (int j = 0; j < KW; j++) {
        int ll = l - (KW - 1) + j;
        if (ll >= 0) {
            size_t idx = ((size_t)(bl - l + ll)) * Dq + c;
            float xq = pq[idx], xk = pk[idx], xv = pv[idx];
            aq += wq[c * KW + j] * xq;
            ak += wk[c * KW + j] * xk;
            av += wv[c * KW + j] * xv;
        }
    }
    // silu
    aq = aq / (1.f + expf(-aq));
    ak = ak / (1.f + expf(-ak));
    av = av / (1.f + expf(-av));

    // block-reduce sum of squares for q and k
    float sq = aq * aq, sk = ak * ak;
#pragma unroll
    for (int off = 16; off > 0; off >>= 1) {
        sq += __shfl_xor_sync(0xffffffffu, sq, off);
        sk += __shfl_xor_sync(0xffffffffu, sk, off);
    }
    __shared__ float shq[4], shk[4];
    const int wid = threadIdx.x >> 5;
    if ((threadIdx.x & 31) == 0) { shq[wid] = sq; shk[wid] = sk; }
    __syncthreads();
    float sumq = shq[0] + shq[1] + shq[2] + shq[3];
    float sumk = shk[0] + shk[1] + shk[2] + shk[3];
    float invq = 1.f / fmaxf(sqrtf(sumq), 1e-12f);
    float invk = 1.f / fmaxf(sqrtf(sumk), 1e-12f);

    size_t base = (size_t)bl * Dq + c;
    oq[base] = aq * invq * 0.08838834764831845f;   // 1/sqrt(128)
    ok[base] = ak * invk;
    ov[base] = av;
}

// ---------------- chunked gated delta-rule scan ----------------
// grid = B*H*2 (split Dv into 2 halves of 64), 256 threads, ~180KB dynamic smem
#define SS_OFF   0
#define SK_OFF   8256
#define SQ_OFF   16512
#define SV_OFF   24768
#define SA_OFF   28928
#define ST_OFF   33088
#define SP_OFF   37248
#define SM_OFF   41408
#define SC_OFF   45568
#define SCAN_SMEM_FLOATS (SC_OFF + 320)
#define SCAN_SMEM_BYTES (SCAN_SMEM_FLOATS * 4)

__global__ __launch_bounds__(256, 1)
void scan_kernel(const float* __restrict__ q, const float* __restrict__ k,
                 const float* __restrict__ v, const float* __restrict__ beta,
                 const float* __restrict__ gdec, const float* __restrict__ S0,
                 float* __restrict__ o, float* __restrict__ Sout)
{
    extern __shared__ float sm[];
    float* sS = sm + SS_OFF;     // [64 dv][129]  (dk)
    float* sK = sm + SK_OFF;     // [64 i][129]
    float* sQ = sm + SQ_OFF;     // [64 i][129]
    float* sV = sm + SV_OFF;     // [64 i][65]
    float* sA = sm + SA_OFF;     // [64][65] (A matrix, later attention)
    float* sT = sm + ST_OFF;     // [64][65]
    float* sP = sm + SP_OFF;     // [64][65] (P, later scaled mid)
    float* sMid = sm + SM_OFF;   // [64][65]
    float* slg = sm + SC_OFF;
    float* sgam = slg + 64;
    float* sgCr = sgam + 64;
    float* sbet = sgCr + 64;
    float* sgg = sbet + 64;

    const int bh = blockIdx.x >> 1;      // b*16+h
    const int grp = blockIdx.x & 1;
    const int b = bh >> 4;
    const int h = bh & 15;
    const int dv0 = grp * 64;
    const int tid = threadIdx.x;

    // init state slice from S0
    for (int idx = tid; idx < 64 * 128; idx += 256) {
        int dv = idx >> 7, dk = idx & 127;
        sS[dv * 129 + dk] = S0[((size_t)bh * 128 + dv0 + dv) * 128 + dk];
    }

    for (int n = 0; n < Nq; n++) {
        const int l0 = n * Cq;
        // load K, Q tiles
        for (int idx = tid; idx < 64 * 128; idx += 256) {
            int i = idx >> 7, d = idx & 127;
            size_t gi = (((size_t)(b * Lq + l0 + i)) * Hq + h) * Dh + d;
            sK[i * 129 + d] = k[gi];
            sQ[i * 129 + d] = q[gi];
        }
        for (int idx = tid; idx < 64 * 64; idx += 256) {
            int i = idx >> 6, dv = idx & 63;
            sV[i * 65 + dv] = v[(((size_t)(b * Lq + l0 + i)) * Hq + h) * Dh + dv0 + dv];
        }
        if (tid < 64) {
            sbet[tid] = beta[(size_t)bh * Lq + l0 + tid];
            sgg[tid] = gdec[(size_t)bh * Lq + l0 + tid];
        }
        __syncthreads();
        if (tid == 0) {
            float c = 0.f;
            for (int i = 0; i < 64; i++) { c += sgg[i]; slg[i] = c; }
        }
        __syncthreads();
        const float lgC = slg[63];
        if (tid < 64) {
            sgam[tid] = expf(slg[tid]);
            sgCr[tid] = expf(lgC - slg[tid]);
        }
        __syncthreads();
        const float gammaC = expf(lgC);

        // A = I + beta_i * exp(lg_i - lg_j) * (K_i . K_j)  (strict lower)
        for (int idx = tid; idx < 4096; idx += 256) {
            int i = idx >> 6, j = idx & 63;
            float val;
            if (j < i) {
                float dot = 0.f;
#pragma unroll 8
                for (int d = 0; d < 128; d++) dot += sK[i * 129 + d] * sK[j * 129 + d];
                val = sbet[i] * expf(slg[i] - slg[j]) * dot;
            } else {
                val = (i == j) ? 1.f : 0.f;
            }
            sA[i * 65 + j] = val;
        }
        __syncthreads();

        // T = A^{-1} : column-parallel forward substitution (no cross-thread deps)
        if (tid < 64) {
            const int j = tid;
            for (int i = 0; i < 64; i++) {
                float s;
                if (i < j) s = 0.f;
                else if (i == j) s = 1.f;
                else {
                    s = 0.f;
                    for (int m = j; m < i; m++) s -= sA[i * 65 + m] * sT[m * 65 + j];
                }
                sT[i * 65 + j] = s;
            }
        }
        __syncthreads();

        // P = beta_i * (V - gamma_i * K @ S^T)
        for (int idx = tid; idx < 4096; idx += 256) {
            int i = idx >> 6, dv = idx & 63;
            float dot = 0.f;
#pragma unroll 8
            for (int d = 0; d < 128; d++) dot += sK[i * 129 + d] * sS[dv * 129 + d];
            sP[i * 65 + dv] = sbet[i] * (sV[i * 65 + dv] - sgam[i] * dot);
        }
        __syncthreads();

        // mid = T @ P
        for (int idx = tid; idx < 4096; idx += 256) {
            int i = idx >> 6, dv = idx & 63;
            float acc = 0.f;
            for (int m = 0; m <= i; m++) acc += sT[i * 65 + m] * sP[m * 65 + dv];
            sMid[i * 65 + dv] = acc;
        }
        __syncthreads();

        // attention matrix: (Q@K^T) * exp(lg_i - lg_j), j <= i
        for (int idx = tid; idx < 4096; idx += 256) {
            int i = idx >> 6, j = idx & 63;
            float val = 0.f;
            if (j <= i) {
                float dot = 0.f;
#pragma unroll 8
                for (int d = 0; d < 128; d++) dot += sQ[i * 129 + d] * sK[j * 129 + d];
                val = expf(slg[i] - slg[j]) * dot;
            }
            sA[i * 65 + j] = val;
        }
        __syncthreads();

        // O = gamma_i * (Q @ S^T) + attn @ mid
        for (int idx = tid; idx < 4096; idx += 256) {
            int i = idx >> 6, dv = idx & 63;
            float acc = 0.f;
#pragma unroll 8
            for (int d = 0; d < 128; d++) acc += sQ[i * 129 + d] * sS[dv * 129 + d];
            acc *= sgam[i];
            float acc2 = 0.f;
            for (int j = 0; j <= i; j++) acc2 += sA[i * 65 + j] * sMid[j * 65 + dv];
            o[(((size_t)(b * Lq + l0 + i)) * Hq + h) * Dh + dv0 + dv] = acc + acc2;
        }
        __syncthreads();

        // scaled mid for state update: P <- mid_i * gCr_i
        for (int idx = tid; idx < 4096; idx += 256) {
            int i = idx >> 6, dv = idx & 63;
            sP[i * 65 + dv] = sMid[i * 65 + dv] * sgCr[i];
        }
        __syncthreads();

        // S = gammaC * S + (scaled mid)^T @ K
        for (int idx = tid; idx < 8192; idx += 256) {
            int dv = idx >> 7, dk = idx & 127;
            float acc = sS[dv * 129 + dk] * gammaC;
#pragma unroll 8
            for (int i = 0; i < 64; i++) acc += sP[i * 65 + dv] * sK[i * 129 + dk];
            sS[dv * 129 + dk] = acc;
        }
        __syncthreads();
    }

    // write final state
    for (int idx = tid; idx < 8192; idx += 256) {
        int dv = idx >> 7, dk = idx & 127;
        Sout[((size_t)bh * 128 + dv0 + dv) * 128 + dk] = sS[dv * 129 + dk];
    }
}

// ---------------- RMSNorm + gate (silu) ----------------
// grid = B*L*H, 128 threads
__global__ void gate_kernel(const float* __restrict__ o, const float* __restrict__ gate,
                            const float* __restrict__ norm_w, float* __restrict__ og)
{
    const size_t base = (size_t)blockIdx.x * Dh + threadIdx.x;
    float ov = o[base];
    float s = ov * ov;
#pragma unroll
    for (int off = 16; off > 0; off >>= 1) s += __shfl_xor_sync(0xffffffffu, s, off);
    __shared__ float sh[4];
    const int wid = threadIdx.x >> 5;
    if ((threadIdx.x & 31) == 0) sh[wid] = s;
    __syncthreads();
    float mean = (sh[0] + sh[1] + sh[2] + sh[3]) * (1.f / 128.f);
    float rs = rsqrtf(mean + EPSq);
    float gv = gate[base];
    float sig = gv / (1.f + expf(-gv));
    og[base] = ov * rs * norm_w[threadIdx.x] * sig;
}

// ---------------- launch ----------------
extern "C" void kernel_launch(void* const* d_in, const int* in_sizes, int n_in,
                              void* d_out, int out_size)
{
    const float* x = (const float*)d_in[0];
    const float* Wq = (const float*)d_in[1];
    const float* Wk = (const float*)d_in[2];
    const float* Wv = (const float*)d_in[3];
    const float* Wb = (const float*)d_in[4];
    const float* Wa = (const float*)d_in[5];
    const float* A_log = (const float*)d_in[6];
    const float* dt_bias = (const float*)d_in[7];
    const float* conv_q = (const float*)d_in[8];
    const float* conv_k = (const float*)d_in[9];
    const float* conv_v = (const float*)d_in[10];
    const float* Wg = (const float*)d_in[11];
    const float* norm_w = (const float*)d_in[12];
    const float* Wo = (const float*)d_in[13];
    const float* S0 = (const float*)d_in[14];

    float* out = (float*)d_out;                 // (B, L, D)
    float* Sout = out + (size_t)BLD;            // (B, H, Dh, Dh)

    float *projq, *projk, *projv, *projg, *qn, *kn, *vn, *beta, *gdec;
    cudaGetSymbolAddress((void**)&projq, g_projq);
    cudaGetSymbolAddress((void**)&projk, g_projk);
    cudaGetSymbolAddress((void**)&projv, g_projv);
    cudaGetSymbolAddress((void**)&projg, g_projg);
    cudaGetSymbolAddress((void**)&qn, g_qn);
    cudaGetSymbolAddress((void**)&kn, g_kn);
    cudaGetSymbolAddress((void**)&vn, g_vn);
    cudaGetSymbolAddress((void**)&beta, g_beta);
    cudaGetSymbolAddress((void**)&gdec, g_gdec);

    float* obuf = projk;    // reuse after conv (projk dead after conv_kernel)
    float* ogbuf = projq;   // reuse after conv

    dim3 ggrid(Dq / 128, BLq / 128);

    // projections
    sgemm_nt<<<ggrid, 256>>>(x, Wq, projq, BLq, Dq, Dq);
    sgemm_nt<<<ggrid, 256>>>(x, Wk, projk, BLq, Dq, Dq);
    sgemm_nt<<<ggrid, 256>>>(x, Wv, projv, BLq, Dq, Dq);
    sgemm_nt<<<ggrid, 256>>>(x, Wg, projg, BLq, Dq, Dq);

    // beta / g
    betag_kernel<<<BLq, 512>>>(x, Wb, Wa, A_log, dt_bias, beta, gdec);

    // conv + silu + l2 norm
    conv_kernel<<<BLq * Hq, 128>>>(projq, projk, projv, conv_q, conv_k, conv_v,
                                   qn, kn, vn);

    // chunked scan
    cudaFuncSetAttribute(scan_kernel, cudaFuncAttributeMaxDynamicSharedMemorySize,
                         SCAN_SMEM_BYTES);
    scan_kernel<<<Bq * Hq * 2, 256, SCAN_SMEM_BYTES>>>(qn, kn, vn, beta, gdec, S0,
                                                       obuf, Sout);

    // gating
    gate_kernel<<<BLq * Hq, 128>>>(obuf, projg, norm_w, ogbuf);

    // output projection
    sgemm_nt<<<ggrid, 256>>>(ogbuf, Wo, out, BLq, Dq, Dq);
}

// round 5
// speedup vs baseline: 1.4244x; 1.4244x over previous
#include <cuda_runtime.h>
#include <cuda_bf16.h>
#include <cstdint>
#include <cstddef>

#define Bq 2
#define Lq 4096
#define Dq 2048
#define Hq 16
#define Dh 128
#define Cq 64
#define Nq (Lq / Cq)
#define KW 4
#define BLq (Bq * Lq)
#define EPSq 1e-5f

#define KS 6144               // split K' = 3*2048
#define NCq 96                // K' / 64 chunks

// ---------------- device scratch buffers ----------------
#define BLD (BLq * Dq)         // 16,777,216
#define BHL (Bq * Hq * Lq)     // 131,072

__device__ float g_projq[BLD];
__device__ float g_projk[BLD];
__device__ float g_projv[BLD];
__device__ float g_projg[BLD];
__device__ float g_qn[BLD];
__device__ float g_kn[BLD];
__device__ float g_vn[BLD];
__device__ float g_beta[BHL];
__device__ float g_gdec[BHL];

__device__ __nv_bfloat16 g_xs[(size_t)BLq * KS];        // split activations (x, then og)
__device__ __nv_bfloat16 g_ws[5][(size_t)Dq * KS];      // split weights Wq,Wk,Wv,Wg,Wo

// ================= helpers =================
__device__ __forceinline__ uint32_t smem_u32(const void* p) {
    uint32_t a;
    asm("{ .reg .u64 t; cvta.to.shared.u64 t, %1; cvt.u32.u64 %0, t; }" : "=r"(a) : "l"(p));
    return a;
}
#define SWZ(x) ((x) ^ (((x) >> 3) & 0x70))

__device__ __forceinline__ void cp16(uint32_t dst, const void* src) {
    asm volatile("cp.async.cg.shared.global [%0], [%1], 16;" :: "r"(dst), "l"(src));
}
__device__ __forceinline__ void ldsm_x4(uint32_t& r0, uint32_t& r1, uint32_t& r2,
                                        uint32_t& r3, uint32_t a) {
    asm volatile("ldmatrix.sync.aligned.m8n8.x4.shared.b16 {%0,%1,%2,%3}, [%4];"
                 : "=r"(r0), "=r"(r1), "=r"(r2), "=r"(r3) : "r"(a));
}
__device__ __forceinline__ void ldsm_x2(uint32_t& r0, uint32_t& r1, uint32_t a) {
    asm volatile("ldmatrix.sync.aligned.m8n8.x2.shared.b16 {%0,%1}, [%2];"
                 : "=r"(r0), "=r"(r1) : "r"(a));
}
__device__ __forceinline__ void mma16816(float* d, const uint32_t* a, const uint32_t* b) {
    asm volatile("mma.sync.aligned.m16n8k16.row.col.f32.bf16.bf16.f32 "
                 "{%0,%1,%2,%3}, {%4,%5,%6,%7}, {%8,%9}, {%0,%1,%2,%3};"
                 : "+f"(d[0]), "+f"(d[1]), "+f"(d[2]), "+f"(d[3])
                 : "r"(a[0]), "r"(a[1]), "r"(a[2]), "r"(a[3]), "r"(b[0]), "r"(b[1]));
}

// ---------------- split conversion: fp32 [rows,2048] -> bf16 [rows,6144] -------
// mode 0 (A side): [hi | hi | lo] ; mode 1 (B side): [hi | lo | hi]
__global__ void split_bf16(const float* __restrict__ in, __nv_bfloat16* __restrict__ out,
                           int mode)
{
    size_t idx = (size_t)blockIdx.x * blockDim.x + threadIdx.x;
    size_t r = idx >> 11;            // /2048
    size_t c = idx & 2047;
    float a = in[idx];
    __nv_bfloat16 hi = __float2bfloat16_rn(a);
    __nv_bfloat16 lo = __float2bfloat16_rn(a - __bfloat162float(hi));
    size_t base = r * KS + c;
    if (mode == 0) {
        out[base] = hi; out[base + 2048] = hi; out[base + 4096] = lo;
    } else {
        out[base] = hi; out[base + 2048] = lo; out[base + 4096] = hi;
    }
}

// ---------------- HMMA GEMM: C[M,2048] = A'[M,KS] * B'[2048,KS]^T --------------
// 128x128 tile / CTA, BK=64, 3-stage cp.async pipeline, 8 warps (2x4) of 64x32.
#define STAGE_B 32768
#define GEMM_SMEM_BYTES (3 * STAGE_B)

__global__ __launch_bounds__(256)
void hmma_gemm(const __nv_bfloat16* __restrict__ A, const __nv_bfloat16* __restrict__ Bw,
               float* __restrict__ C)
{
    extern __shared__ __align__(128) char smem[];
    const uint32_t sb = smem_u32(smem);
    const int tid = threadIdx.x;
    const int warp = tid >> 5, lane = tid & 31;
    const int wm = warp & 1, wn = warp >> 1;
    const int bm = blockIdx.y * 128, bn = blockIdx.x * 128;

    const __nv_bfloat16* Abase = A + (size_t)bm * KS;
    const __nv_bfloat16* Bbase = Bw + (size_t)bn * KS;

    float acc[4][4][4];
#pragma unroll
    for (int i = 0; i < 4; i++)
#pragma unroll
        for (int j = 0; j < 4; j++)
#pragma unroll
            for (int r = 0; r < 4; r++) acc[i][j][r] = 0.f;

    // per-thread load slots: 4 x 16B per operand per stage
    const int lrow = tid >> 3;            // 0..31 base row
    const int lseg = tid & 7;
    const uint32_t loff = SWZ(lrow * 128 + lseg * 16);

#define LOAD_STAGE(s, kc) do { \
        uint32_t _as = sb + (s) * STAGE_B; \
        uint32_t _bs = _as + 16384; \
        const __nv_bfloat16* _ap = Abase + (size_t)lrow * KS + (size_t)(kc) * 64 + lseg * 8; \
        const __nv_bfloat16* _bp = Bbase + (size_t)lrow * KS + (size_t)(kc) * 64 + lseg * 8; \
        _Pragma("unroll") \
        for (int _i = 0; _i < 4; _i++) { \
            cp16(_as + loff + _i * 4096, _ap + (size_t)_i * 32 * KS); \
            cp16(_bs + loff + _i * 4096, _bp + (size_t)_i * 32 * KS); \
        } \
        asm volatile("cp.async.commit_group;" ::: "memory"); \
    } while (0)

    // precomputed fragment addresses (stage-relative)
    const int aq = lane >> 3;
    const int am = (lane & 7) + (aq & 1) * 8;
    const int akb = (aq >> 1) * 8;
    const int bl = lane & 15;
    const int bn8 = bl & 7;
    const int bkb = (bl >> 3) * 8;

    LOAD_STAGE(0, 0);
    LOAD_STAGE(1, 1);

    for (int c = 0; c < NCq; c++) {
        if (c == NCq - 1) {
            asm volatile("cp.async.wait_group 0;" ::: "memory");
        } else {
            asm volatile("cp.async.wait_group 1;" ::: "memory");
        }
        __syncthreads();
        if (c + 2 < NCq) LOAD_STAGE((c + 2) % 3, c + 2);

        const uint32_t As = sb + (c % 3) * STAGE_B;
        const uint32_t Bs = As + 16384;
#pragma unroll
        for (int ks = 0; ks < 4; ks++) {
            const int k0 = ks * 16;
            uint32_t af[4][4];
#pragma unroll
            for (int mt = 0; mt < 4; mt++) {
                int m = wm * 64 + mt * 16 + am;
                ldsm_x4(af[mt][0], af[mt][1], af[mt][2], af[mt][3],
                        As + SWZ(m * 128 + (k0 + akb) * 2));
            }
            uint32_t bf[4][2];
#pragma unroll
            for (int nt = 0; nt < 4; nt++) {
                int n = wn * 32 + nt * 8 + bn8;
                ldsm_x2(bf[nt][0], bf[nt][1],
                        Bs + SWZ(n * 128 + (k0 + bkb) * 2));
            }
#pragma unroll
            for (int mt = 0; mt < 4; mt++)
#pragma unroll
                for (int nt = 0; nt < 4; nt++)
                    mma16816(acc[mt][nt], af[mt], bf[nt]);
        }
    }

    // epilogue
    const int r0 = bm + wm * 64 + (lane >> 2);
    const int c0 = bn + wn * 32 + (lane & 3) * 2;
#pragma unroll
    for (int mt = 0; mt < 4; mt++) {
#pragma unroll
        for (int nt = 0; nt < 4; nt++) {
            float2* p0 = (float2*)(C + (size_t)(r0 + mt * 16) * Dq + c0 + nt * 8);
            float2* p1 = (float2*)(C + (size_t)(r0 + mt * 16 + 8) * Dq + c0 + nt * 8);
            *p0 = make_float2(acc[mt][nt][0], acc[mt][nt][1]);
            *p1 = make_float2(acc[mt][nt][2], acc[mt][nt][3]);
        }
    }
}

// ---------------- beta / g kernel ----------------
__global__ void betag_kernel(const float* __restrict__ x,
                             const float* __restrict__ Wb,
                             const float* __restrict__ Wa,
                             const float* __restrict__ A_log,
                             const float* __restrict__ dt_bias,
                             float* __restrict__ beta,
                             float* __restrict__ gdec)
{
    const int bl = blockIdx.x;
    const int h = threadIdx.x >> 5;
    const int lane = threadIdx.x & 31;
    const float* xr = x + (size_t)bl * Dq;
    const float* wb = Wb + (size_t)h * Dq;
    const float* wa = Wa + (size_t)h * Dq;
    float sb = 0.f, sa = 0.f;
    for (int i = lane; i < Dq; i += 32) {
        float xv = xr[i];
        sb += xv * wb[i];
        sa += xv * wa[i];
    }
#pragma unroll
    for (int off = 16; off > 0; off >>= 1) {
        sb += __shfl_down_sync(0xffffffffu, sb, off);
        sa += __shfl_down_sync(0xffffffffu, sa, off);
    }
    if (lane == 0) {
        const int b = bl / Lq, l = bl % Lq;
        float bet = 1.f / (1.f + expf(-sb));
        float z = sa + dt_bias[h];
        float sp = (z > 15.f) ? z : log1pf(expf(z));
        float g = -expf(A_log[h]) * sp;
        size_t o = ((size_t)(b * Hq + h)) * Lq + l;
        beta[o] = bet;
        gdec[o] = g;
    }
}

// ---------------- causal dwconv + silu + l2 norm ----------------
__global__ void conv_kernel(const float* __restrict__ pq, const float* __restrict__ pk,
                            const float* __restrict__ pv,
                            const float* __restrict__ wq, const float* __restrict__ wk,
                            const float* __restrict__ wv,
                            float* __restrict__ oq, float* __restrict__ ok,
                            float* __restrict__ ov)
{
    const int blk = blockIdx.x;
    const int h = blk % Hq;
    const int bl = blk / Hq;
    const int l = bl % Lq;
    const int d = threadIdx.x;
    const int c = h * Dh + d;

    float aq = 0.f, ak = 0.f, av = 0.f;
#pragma unroll
    for (int j = 0; j < KW; j++) {
        int ll = l - (KW - 1) + j;
        if (ll >= 0) {
            size_t idx = ((size_t)(bl - l + ll)) * Dq + c;
            float xq = pq[idx], xk = pk[idx], xv = pv[idx];
            aq += wq[c * KW + j] * xq;
            ak += wk[c * KW + j] * xk;
            av += wv[c * KW + j] * xv;
        }
    }
    aq = aq / (1.f + expf(-aq));
    ak = ak / (1.f + expf(-ak));
    av = av / (1.f + expf(-av));

    float sq = aq * aq, sk = ak * ak;
#pragma unroll
    for (int off = 16; off > 0; off >>= 1) {
        sq += __shfl_xor_sync(0xffffffffu, sq, off);
        sk += __shfl_xor_sync(0xffffffffu, sk, off);
    }
    __shared__ float shq[4], shk[4];
    const int wid = threadIdx.x >> 5;
    if ((threadIdx.x & 31) == 0) { shq[wid] = sq; shk[wid] = sk; }
    __syncthreads();
    float sumq = shq[0] + shq[1] + shq[2] + shq[3];
    float sumk = shk[0] + shk[1] + shk[2] + shk[3];
    float invq = 1.f / fmaxf(sqrtf(sumq), 1e-12f);
    float invk = 1.f / fmaxf(sqrtf(sumk), 1e-12f);

    size_t base = (size_t)bl * Dq + c;
    oq[base] = aq * invq * 0.08838834764831845f;
    ok[base] = ak * invk;
    ov[base] = av;
}

// ---------------- chunked gated delta-rule scan ----------------
#define SS_OFF   0
#define SK_OFF   8256
#define SQ_OFF   16512
#define SV_OFF   24768
#define SA_OFF   28928
#define ST_OFF   33088
#define SP_OFF   37248
#define SM_OFF   41408
#define SC_OFF   45568
#define SCAN_SMEM_FLOATS (SC_OFF + 320)
#define SCAN_SMEM_BYTES (SCAN_SMEM_FLOATS * 4)

__global__ __launch_bounds__(256, 1)
void scan_kernel(const float* __restrict__ q, const float* __restrict__ k,
                 const float* __restrict__ v, const float* __restrict__ beta,
                 const float* __restrict__ gdec, const float* __restrict__ S0,
                 float* __restrict__ o, float* __restrict__ Sout)
{
    extern __shared__ float sm[];
    float* sS = sm + SS_OFF;
    float* sK = sm + SK_OFF;
    float* sQ = sm + SQ_OFF;
    float* sV = sm + SV_OFF;
    float* sA = sm + SA_OFF;
    float* sT = sm + ST_OFF;
    float* sP = sm + SP_OFF;
    float* sMid = sm + SM_OFF;
    float* slg = sm + SC_OFF;
    float* sgam = slg + 64;
    float* sgCr = sgam + 64;
    float* sbet = sgCr + 64;
    float* sgg = sbet + 64;

    const int bh = blockIdx.x >> 1;
    const int grp = blockIdx.x & 1;
    const int b = bh >> 4;
    const int h = bh & 15;
    const int dv0 = grp * 64;
    const int tid = threadIdx.x;

    for (int idx = tid; idx < 64 * 128; idx += 256) {
        int dv = idx >> 7, dk = idx & 127;
        sS[dv * 129 + dk] = S0[((size_t)bh * 128 + dv0 + dv) * 128 + dk];
    }

    for (int n = 0; n < Nq; n++) {
        const int l0 = n * Cq;
        for (int idx = tid; idx < 64 * 128; idx += 256) {
            int i = idx >> 7, d = idx & 127;
            size_t gi = (((size_t)(b * Lq + l0 + i)) * Hq + h) * Dh + d;
            sK[i * 129 + d] = k[gi];
            sQ[i * 129 + d] = q[gi];
        }
        for (int idx = tid; idx < 64 * 64; idx += 256) {
            int i = idx >> 6, dv = idx & 63;
            sV[i * 65 + dv] = v[(((size_t)(b * Lq + l0 + i)) * Hq + h) * Dh + dv0 + dv];
        }
        if (tid < 64) {
            sbet[tid] = beta[(size_t)bh * Lq + l0 + tid];
            sgg[tid] = gdec[(size_t)bh * Lq + l0 + tid];
        }
        __syncthreads();
        if (tid == 0) {
            float c = 0.f;
            for (int i = 0; i < 64; i++) { c += sgg[i]; slg[i] = c; }
        }
        __syncthreads();
        const float lgC = slg[63];
        if (tid < 64) {
            sgam[tid] = expf(slg[tid]);
            sgCr[tid] = expf(lgC - slg[tid]);
        }
        __syncthreads();
        const float gammaC = expf(lgC);

        for (int idx = tid; idx < 4096; idx += 256) {
            int i = idx >> 6, j = idx & 63;
            float val;
            if (j < i) {
                float dot = 0.f;
#pragma unroll 8
                for (int d = 0; d < 128; d++) dot += sK[i * 129 + d] * sK[j * 129 + d];
                val = sbet[i] * expf(slg[i] - slg[j]) * dot;
            } else {
                val = (i == j) ? 1.f : 0.f;
            }
            sA[i * 65 + j] = val;
        }
        __syncthreads();

        if (tid < 64) {
            const int j = tid;
            for (int i = 0; i < 64; i++) {
                float s;
                if (i < j) s = 0.f;
                else if (i == j) s = 1.f;
                else {
                    s = 0.f;
                    for (int m = j; m < i; m++) s -= sA[i * 65 + m] * sT[m * 65 + j];
                }
                sT[i * 65 + j] = s;
            }
        }
        __syncthreads();

        for (int idx = tid; idx < 4096; idx += 256) {
            int i = idx >> 6, dv = idx & 63;
            float dot = 0.f;
#pragma unroll 8
            for (int d = 0; d < 128; d++) dot += sK[i * 129 + d] * sS[dv * 129 + d];
            sP[i * 65 + dv] = sbet[i] * (sV[i * 65 + dv] - sgam[i] * dot);
        }
        __syncthreads();

        for (int idx = tid; idx < 4096; idx += 256) {
            int i = idx >> 6, dv = idx & 63;
            float acc = 0.f;
            for (int m = 0; m <= i; m++) acc += sT[i * 65 + m] * sP[m * 65 + dv];
            sMid[i * 65 + dv] = acc;
        }
        __syncthreads();

        for (int idx = tid; idx < 4096; idx += 256) {
            int i = idx >> 6, j = idx & 63;
            float val = 0.f;
            if (j <= i) {
                float dot = 0.f;
#pragma unroll 8
                for (int d = 0; d < 128; d++) dot += sQ[i * 129 + d] * sK[j * 129 + d];
                val = expf(slg[i] - slg[j]) * dot;
            }
            sA[i * 65 + j] = val;
        }
        __syncthreads();

        for (int idx = tid; idx < 4096; idx += 256) {
            int i = idx >> 6, dv = idx & 63;
            float acc = 0.f;
#pragma unroll 8
            for (int d = 0; d < 128; d++) acc += sQ[i * 129 + d] * sS[dv * 129 + d];
            acc *= sgam[i];
            float acc2 = 0.f;
            for (int j = 0; j <= i; j++) acc2 += sA[i * 65 + j] * sMid[j * 65 + dv];
            o[(((size_t)(b * Lq + l0 + i)) * Hq + h) * Dh + dv0 + dv] = acc + acc2;
        }
        __syncthreads();

        for (int idx = tid; idx < 4096; idx += 256) {
            int i = idx >> 6, dv = idx & 63;
            sP[i * 65 + dv] = sMid[i * 65 + dv] * sgCr[i];
        }
        __syncthreads();

        for (int idx = tid; idx < 8192; idx += 256) {
            int dv = idx >> 7, dk = idx & 127;
            float acc = sS[dv * 129 + dk] * gammaC;
#pragma unroll 8
            for (int i = 0; i < 64; i++) acc += sP[i * 65 + dv] * sK[i * 129 + dk];
            sS[dv * 129 + dk] = acc;
        }
        __syncthreads();
    }

    for (int idx = tid; idx < 8192; idx += 256) {
        int dv = idx >> 7, dk = idx & 127;
        Sout[((size_t)bh * 128 + dv0 + dv) * 128 + dk] = sS[dv * 129 + dk];
    }
}

// ---------------- RMSNorm + gate (silu) ----------------
__global__ void gate_kernel(const float* __restrict__ o, const float* __restrict__ gate,
                            const float* __restrict__ norm_w, float* __restrict__ og)
{
    const size_t base = (size_t)blockIdx.x * Dh + threadIdx.x;
    float ov = o[base];
    float s = ov * ov;
#pragma unroll
    for (int off = 16; off > 0; off >>= 1) s += __shfl_xor_sync(0xffffffffu, s, off);
    __shared__ float sh[4];
    const int wid = threadIdx.x >> 5;
    if ((threadIdx.x & 31) == 0) sh[wid] = s;
    __syncthreads();
    float mean = (sh[0] + sh[1] + sh[2] + sh[3]) * (1.f / 128.f);
    float rs = rsqrtf(mean + EPSq);
    float gv = gate[base];
    float sig = gv / (1.f + expf(-gv));
    og[base] = ov * rs * norm_w[threadIdx.x] * sig;
}

// ---------------- launch ----------------
extern "C" void kernel_launch(void* const* d_in, const int* in_sizes, int n_in,
                              void* d_out, int out_size)
{
    const float* x = (const float*)d_in[0];
    const float* Wq = (const float*)d_in[1];
    const float* Wk = (const float*)d_in[2];
    const float* Wv = (const float*)d_in[3];
    const float* Wb = (const float*)d_in[4];
    const float* Wa = (const float*)d_in[5];
    const float* A_log = (const float*)d_in[6];
    const float* dt_bias = (const float*)d_in[7];
    const float* conv_q = (const float*)d_in[8];
    const float* conv_k = (const float*)d_in[9];
    const float* conv_v = (const float*)d_in[10];
    const float* Wg = (const float*)d_in[11];
    const float* norm_w = (const float*)d_in[12];
    const float* Wo = (const float*)d_in[13];
    const float* S0 = (const float*)d_in[14];

    float* out = (float*)d_out;
    float* Sout = out + (size_t)BLD;

    float *projq, *projk, *projv, *projg, *qn, *kn, *vn, *beta, *gdec;
    __nv_bfloat16 *xs, *ws;
    cudaGetSymbolAddress((void**)&projq, g_projq);
    cudaGetSymbolAddress((void**)&projk, g_projk);
    cudaGetSymbolAddress((void**)&projv, g_projv);
    cudaGetSymbolAddress((void**)&projg, g_projg);
    cudaGetSymbolAddress((void**)&qn, g_qn);
    cudaGetSymbolAddress((void**)&kn, g_kn);
    cudaGetSymbolAddress((void**)&vn, g_vn);
    cudaGetSymbolAddress((void**)&beta, g_beta);
    cudaGetSymbolAddress((void**)&gdec, g_gdec);
    cudaGetSymbolAddress((void**)&xs, g_xs);
    cudaGetSymbolAddress((void**)&ws, g_ws);

    __nv_bfloat16* wsq = ws;
    __nv_bfloat16* wsk = ws + 1 * (size_t)Dq * KS;
    __nv_bfloat16* wsv = ws + 2 * (size_t)Dq * KS;
    __nv_bfloat16* wsg = ws + 3 * (size_t)Dq * KS;
    __nv_bfloat16* wso = ws + 4 * (size_t)Dq * KS;

    float* obuf = projk;
    float* ogbuf = projq;

    cudaFuncSetAttribute(scan_kernel, cudaFuncAttributeMaxDynamicSharedMemorySize,
                         SCAN_SMEM_BYTES);
    cudaFuncSetAttribute(hmma_gemm, cudaFuncAttributeMaxDynamicSharedMemorySize,
                         GEMM_SMEM_BYTES);

    // split conversions
    split_bf16<<<BLD / 256, 256>>>(x, xs, 0);
    split_bf16<<<(Dq * Dq) / 256, 256>>>(Wq, wsq, 1);
    split_bf16<<<(Dq * Dq) / 256, 256>>>(Wk, wsk, 1);
    split_bf16<<<(Dq * Dq) / 256, 256>>>(Wv, wsv, 1);
    split_bf16<<<(Dq * Dq) / 256, 256>>>(Wg, wsg, 1);
    split_bf16<<<(Dq * Dq) / 256, 256>>>(Wo, wso, 1);

    dim3 ggrid(Dq / 128, BLq / 128);   // (16, 64)

    // projections via tensor cores (mma.sync bf16, split-3 for fp32-level accuracy)
    hmma_gemm<<<ggrid, 256, GEMM_SMEM_BYTES>>>(xs, wsq, projq);
    hmma_gemm<<<ggrid, 256, GEMM_SMEM_BYTES>>>(xs, wsk, projk);
    hmma_gemm<<<ggrid, 256, GEMM_SMEM_BYTES>>>(xs, wsv, projv);
    hmma_gemm<<<ggrid, 256, GEMM_SMEM_BYTES>>>(xs, wsg, projg);

    betag_kernel<<<BLq, 512>>>(x, Wb, Wa, A_log, dt_bias, beta, gdec);

    conv_kernel<<<BLq * Hq, 128>>>(projq, projk, projv, conv_q, conv_k, conv_v,
                                   qn, kn, vn);

    scan_kernel<<<Bq * Hq * 2, 256, SCAN_SMEM_BYTES>>>(qn, kn, vn, beta, gdec, S0,
                                                       obuf, Sout);

    gate_kernel<<<BLq * Hq, 128>>>(obuf, projg, norm_w, ogbuf);

    // output projection (reuse xs for split og)
    split_bf16<<<BLD / 256, 256>>>(ogbuf, xs, 0);
    hmma_gemm<<<ggrid, 256, GEMM_SMEM_BYTES>>>(xs, wso, out);
}

// round 6
// speedup vs baseline: 2.7119x; 1.9039x over previous
#include <cuda_runtime.h>
#include <cuda_bf16.h>
#include <cstdint>
#include <cstddef>

#define Bq 2
#define Lq 4096
#define Dq 2048
#define Hq 16
#define Dh 128
#define Cq 64
#define Nq (Lq / Cq)
#define KW 4
#define BLq (Bq * Lq)
#define EPSq 1e-5f

#define KS 6144               // split K' = 3*2048
#define NCq 96                // K' / 64 chunks

// ---------------- device scratch buffers ----------------
#define BLD (BLq * Dq)         // 16,777,216
#define BHL (Bq * Hq * Lq)     // 131,072

__device__ float g_projq[BLD];
__device__ float g_projk[BLD];
__device__ float g_projv[BLD];
__device__ float g_projg[BLD];
__device__ float g_qn[BLD];
__device__ float g_kn[BLD];
__device__ float g_vn[BLD];
__device__ float g_beta[BHL];
__device__ float g_gdec[BHL];

__device__ __nv_bfloat16 g_xs[(size_t)BLq * KS];        // split activations (x, then og)
__device__ __nv_bfloat16 g_ws[5][(size_t)Dq * KS];      // split weights Wq,Wk,Wv,Wg,Wo

// ================= helpers =================
__device__ __forceinline__ uint32_t smem_u32(const void* p) {
    uint32_t a;
    asm("{ .reg .u64 t; cvta.to.shared.u64 t, %1; cvt.u32.u64 %0, t; }" : "=r"(a) : "l"(p));
    return a;
}
#define SWZ(x) ((x) ^ (((x) >> 3) & 0x70))

__device__ __forceinline__ void cp16(uint32_t dst, const void* src) {
    asm volatile("cp.async.cg.shared.global [%0], [%1], 16;" :: "r"(dst), "l"(src));
}
__device__ __forceinline__ void ldsm_x4(uint32_t& r0, uint32_t& r1, uint32_t& r2,
                                        uint32_t& r3, uint32_t a) {
    asm volatile("ldmatrix.sync.aligned.m8n8.x4.shared.b16 {%0,%1,%2,%3}, [%4];"
                 : "=r"(r0), "=r"(r1), "=r"(r2), "=r"(r3) : "r"(a));
}
__device__ __forceinline__ void ldsm_x2(uint32_t& r0, uint32_t& r1, uint32_t a) {
    asm volatile("ldmatrix.sync.aligned.m8n8.x2.shared.b16 {%0,%1}, [%2];"
                 : "=r"(r0), "=r"(r1) : "r"(a));
}
__device__ __forceinline__ void mma16816(float* d, const uint32_t* a, const uint32_t* b) {
    asm volatile("mma.sync.aligned.m16n8k16.row.col.f32.bf16.bf16.f32 "
                 "{%0,%1,%2,%3}, {%4,%5,%6,%7}, {%8,%9}, {%0,%1,%2,%3};"
                 : "+f"(d[0]), "+f"(d[1]), "+f"(d[2]), "+f"(d[3])
                 : "r"(a[0]), "r"(a[1]), "r"(a[2]), "r"(a[3]), "r"(b[0]), "r"(b[1]));
}
__device__ __forceinline__ float dot4(float4 a, float4 b) {
    return a.x * b.x + a.y * b.y + a.z * b.z + a.w * b.w;
}

// ---------------- split conversion: fp32 [rows,2048] -> bf16 [rows,6144] -------
__global__ void split_bf16(const float* __restrict__ in, __nv_bfloat16* __restrict__ out,
                           int mode)
{
    size_t idx = (size_t)blockIdx.x * blockDim.x + threadIdx.x;
    size_t r = idx >> 11;
    size_t c = idx & 2047;
    float a = in[idx];
    __nv_bfloat16 hi = __float2bfloat16_rn(a);
    __nv_bfloat16 lo = __float2bfloat16_rn(a - __bfloat162float(hi));
    size_t base = r * KS + c;
    if (mode == 0) {
        out[base] = hi; out[base + 2048] = hi; out[base + 4096] = lo;
    } else {
        out[base] = hi; out[base + 2048] = lo; out[base + 4096] = hi;
    }
}

// ---------------- HMMA GEMM: C[M,2048] = A'[M,KS] * B'[2048,KS]^T --------------
#define STAGE_B 32768
#define GEMM_SMEM_BYTES (3 * STAGE_B)

__global__ __launch_bounds__(256, 2)
void hmma_gemm(const __nv_bfloat16* __restrict__ A, const __nv_bfloat16* __restrict__ Bw,
               float* __restrict__ C)
{
    extern __shared__ __align__(128) char smem[];
    const uint32_t sb = smem_u32(smem);
    const int tid = threadIdx.x;
    const int warp = tid >> 5, lane = tid & 31;
    const int wm = warp & 1, wn = warp >> 1;
    const int bm = blockIdx.y * 128, bn = blockIdx.x * 128;

    const __nv_bfloat16* Abase = A + (size_t)bm * KS;
    const __nv_bfloat16* Bbase = Bw + (size_t)bn * KS;

    float acc[4][4][4];
#pragma unroll
    for (int i = 0; i < 4; i++)
#pragma unroll
        for (int j = 0; j < 4; j++)
#pragma unroll
            for (int r = 0; r < 4; r++) acc[i][j][r] = 0.f;

    const int lrow = tid >> 3;
    const int lseg = tid & 7;
    const uint32_t loff = SWZ(lrow * 128 + lseg * 16);

#define LOAD_STAGE(s, kc) do { \
        uint32_t _as = sb + (s) * STAGE_B; \
        uint32_t _bs = _as + 16384; \
        const __nv_bfloat16* _ap = Abase + (size_t)lrow * KS + (size_t)(kc) * 64 + lseg * 8; \
        const __nv_bfloat16* _bp = Bbase + (size_t)lrow * KS + (size_t)(kc) * 64 + lseg * 8; \
        _Pragma("unroll") \
        for (int _i = 0; _i < 4; _i++) { \
            cp16(_as + loff + _i * 4096, _ap + (size_t)_i * 32 * KS); \
            cp16(_bs + loff + _i * 4096, _bp + (size_t)_i * 32 * KS); \
        } \
        asm volatile("cp.async.commit_group;" ::: "memory"); \
    } while (0)

    const int aq = lane >> 3;
    const int am = (lane & 7) + (aq & 1) * 8;
    const int akb = (aq >> 1) * 8;
    const int bl = lane & 15;
    const int bn8 = bl & 7;
    const int bkb = (bl >> 3) * 8;

    LOAD_STAGE(0, 0);
    LOAD_STAGE(1, 1);

    for (int c = 0; c < NCq; c++) {
        if (c == NCq - 1) {
            asm volatile("cp.async.wait_group 0;" ::: "memory");
        } else {
            asm volatile("cp.async.wait_group 1;" ::: "memory");
        }
        __syncthreads();
        if (c + 2 < NCq) LOAD_STAGE((c + 2) % 3, c + 2);

        const uint32_t As = sb + (c % 3) * STAGE_B;
        const uint32_t Bs = As + 16384;
#pragma unroll
        for (int ks = 0; ks < 4; ks++) {
            const int k0 = ks * 16;
            uint32_t af[4][4];
#pragma unroll
            for (int mt = 0; mt < 4; mt++) {
                int m = wm * 64 + mt * 16 + am;
                ldsm_x4(af[mt][0], af[mt][1], af[mt][2], af[mt][3],
                        As + SWZ(m * 128 + (k0 + akb) * 2));
            }
            uint32_t bf[4][2];
#pragma unroll
            for (int nt = 0; nt < 4; nt++) {
                int n = wn * 32 + nt * 8 + bn8;
                ldsm_x2(bf[nt][0], bf[nt][1],
                        Bs + SWZ(n * 128 + (k0 + bkb) * 2));
            }
#pragma unroll
            for (int mt = 0; mt < 4; mt++)
#pragma unroll
                for (int nt = 0; nt < 4; nt++)
                    mma16816(acc[mt][nt], af[mt], bf[nt]);
        }
    }

    const int r0 = bm + wm * 64 + (lane >> 2);
    const int c0 = bn + wn * 32 + (lane & 3) * 2;
#pragma unroll
    for (int mt = 0; mt < 4; mt++) {
#pragma unroll
        for (int nt = 0; nt < 4; nt++) {
            float2* p0 = (float2*)(C + (size_t)(r0 + mt * 16) * Dq + c0 + nt * 8);
            float2* p1 = (float2*)(C + (size_t)(r0 + mt * 16 + 8) * Dq + c0 + nt * 8);
            *p0 = make_float2(acc[mt][nt][0], acc[mt][nt][1]);
            *p1 = make_float2(acc[mt][nt][2], acc[mt][nt][3]);
        }
    }
}

// ---------------- beta / g kernel ----------------
__global__ void betag_kernel(const float* __restrict__ x,
                             const float* __restrict__ Wb,
                             const float* __restrict__ Wa,
                             const float* __restrict__ A_log,
                             const float* __restrict__ dt_bias,
                             float* __restrict__ beta,
                             float* __restrict__ gdec)
{
    const int bl = blockIdx.x;
    const int h = threadIdx.x >> 5;
    const int lane = threadIdx.x & 31;
    const float* xr = x + (size_t)bl * Dq;
    const float* wb = Wb + (size_t)h * Dq;
    const float* wa = Wa + (size_t)h * Dq;
    float sb = 0.f, sa = 0.f;
    for (int i = lane; i < Dq; i += 32) {
        float xv = xr[i];
        sb += xv * wb[i];
        sa += xv * wa[i];
    }
#pragma unroll
    for (int off = 16; off > 0; off >>= 1) {
        sb += __shfl_down_sync(0xffffffffu, sb, off);
        sa += __shfl_down_sync(0xffffffffu, sa, off);
    }
    if (lane == 0) {
        const int b = bl / Lq, l = bl % Lq;
        float bet = 1.f / (1.f + expf(-sb));
        float z = sa + dt_bias[h];
        float sp = (z > 15.f) ? z : log1pf(expf(z));
        float g = -expf(A_log[h]) * sp;
        size_t o = ((size_t)(b * Hq + h)) * Lq + l;
        beta[o] = bet;
        gdec[o] = g;
    }
}

// ---------------- causal dwconv + silu + l2 norm ----------------
__global__ void conv_kernel(const float* __restrict__ pq, const float* __restrict__ pk,
                            const float* __restrict__ pv,
                            const float* __restrict__ wq, const float* __restrict__ wk,
                            const float* __restrict__ wv,
                            float* __restrict__ oq, float* __restrict__ ok,
                            float* __restrict__ ov)
{
    const int blk = blockIdx.x;
    const int h = blk % Hq;
    const int bl = blk / Hq;
    const int l = bl % Lq;
    const int d = threadIdx.x;
    const int c = h * Dh + d;

    float aq = 0.f, ak = 0.f, av = 0.f;
#pragma unroll
    for (int j = 0; j < KW; j++) {
        int ll = l - (KW - 1) + j;
        if (ll >= 0) {
            size_t idx = ((size_t)(bl - l + ll)) * Dq + c;
            float xq = pq[idx], xk = pk[idx], xv = pv[idx];
            aq += wq[c * KW + j] * xq;
            ak += wk[c * KW + j] * xk;
            av += wv[c * KW + j] * xv;
        }
    }
    aq = aq / (1.f + expf(-aq));
    ak = ak / (1.f + expf(-ak));
    av = av / (1.f + expf(-av));

    float sq = aq * aq, sk = ak * ak;
#pragma unroll
    for (int off = 16; off > 0; off >>= 1) {
        sq += __shfl_xor_sync(0xffffffffu, sq, off);
        sk += __shfl_xor_sync(0xffffffffu, sk, off);
    }
    __shared__ float shq[4], shk[4];
    const int wid = threadIdx.x >> 5;
    if ((threadIdx.x & 31) == 0) { shq[wid] = sq; shk[wid] = sk; }
    __syncthreads();
    float sumq = shq[0] + shq[1] + shq[2] + shq[3];
    float sumk = shk[0] + shk[1] + shk[2] + shk[3];
    float invq = 1.f / fmaxf(sqrtf(sumq), 1e-12f);
    float invk = 1.f / fmaxf(sqrtf(sumk), 1e-12f);

    size_t base = (size_t)bl * Dq + c;
    oq[base] = aq * invq * 0.08838834764831845f;
    ok[base] = ak * invk;
    ov[base] = av;
}

// ---------------- chunked gated delta-rule scan (register-tiled) ----------------
// grid = B*H*4 (Dv split into 4 groups of 32), 256 threads
#define SKT 132          // stride for K/Q/S rows (d index), float4-aligned
#define SAT 68           // stride for A/T rows (j index)
#define SVT 36           // stride for V/P/Mid rows (dv index, 32 cols)

#define SK_OFF  0
#define SQ_OFF  8448
#define SS_OFF  16896
#define SA_OFF  21120
#define ST_OFF  25472
#define SV_OFF  29824
#define SP_OFF  32128
#define SM_OFF  34432
#define SC_OFF  36736
#define SCAN_SMEM_FLOATS (SC_OFF + 320)
#define SCAN_SMEM_BYTES (SCAN_SMEM_FLOATS * 4)

__global__ __launch_bounds__(256, 1)
void scan_kernel(const float* __restrict__ q, const float* __restrict__ k,
                 const float* __restrict__ v, const float* __restrict__ beta,
                 const float* __restrict__ gdec, const float* __restrict__ S0,
                 float* __restrict__ o, float* __restrict__ Sout)
{
    extern __shared__ float sm[];
    float* sK = sm + SK_OFF;     // [64 i][SKT] (d=128)
    float* sQ = sm + SQ_OFF;     // [64 i][SKT]
    float* sS = sm + SS_OFF;     // [32 dv][SKT] (dk=128)
    float* sA = sm + SA_OFF;     // [64][SAT]
    float* sT = sm + ST_OFF;     // [64][SAT]
    float* sV = sm + SV_OFF;     // [64 i][SVT] (dv=32)
    float* sP = sm + SP_OFF;     // [64 i][SVT]
    float* sMid = sm + SM_OFF;   // [64 i][SVT]
    float* slg = sm + SC_OFF;
    float* sgam = slg + 64;
    float* sgCr = sgam + 64;
    float* sbet = sgCr + 64;
    float* sgg = sbet + 64;

    const int bh = blockIdx.x >> 2;      // b*16+h
    const int grp = blockIdx.x & 3;
    const int b = bh >> 4;
    const int h = bh & 15;
    const int dv0 = grp * 32;
    const int tid = threadIdx.x;
    const int t_hi = tid >> 4;           // 0..15
    const int t_lo = tid & 15;           // 0..15

    // init state slice [32][128] from S0
    for (int idx = tid; idx < 32 * 128; idx += 256) {
        int dv = idx >> 7, dk = idx & 127;
        sS[dv * SKT + dk] = S0[((size_t)bh * 128 + dv0 + dv) * 128 + dk];
    }

    for (int n = 0; n < Nq; n++) {
        const int l0 = n * Cq;
        for (int idx = tid; idx < 64 * 128; idx += 256) {
            int i = idx >> 7, d = idx & 127;
            size_t gi = (((size_t)(b * Lq + l0 + i)) * Hq + h) * Dh + d;
            sK[i * SKT + d] = k[gi];
            sQ[i * SKT + d] = q[gi];
        }
        for (int idx = tid; idx < 64 * 32; idx += 256) {
            int i = idx >> 5, dv = idx & 31;
            sV[i * SVT + dv] = v[(((size_t)(b * Lq + l0 + i)) * Hq + h) * Dh + dv0 + dv];
        }
        if (tid < 64) {
            sbet[tid] = beta[(size_t)bh * Lq + l0 + tid];
            sgg[tid] = gdec[(size_t)bh * Lq + l0 + tid];
        }
        __syncthreads();
        if (tid == 0) {
            float c = 0.f;
            for (int i = 0; i < 64; i++) { c += sgg[i]; slg[i] = c; }
        }
        __syncthreads();
        const float lgC = slg[63];
        if (tid < 64) {
            sgam[tid] = expf(slg[tid]);
            sgCr[tid] = expf(lgC - slg[tid]);
        }
        __syncthreads();
        const float gammaC = expf(lgC);

        // ---- A = I + beta_i * exp(lg_i - lg_j) * (K_i . K_j) (strict lower) ----
        {
            float acc[4][4];
#pragma unroll
            for (int r = 0; r < 4; r++)
#pragma unroll
                for (int c = 0; c < 4; c++) acc[r][c] = 0.f;
            for (int d = 0; d < 128; d += 4) {
                float4 av[4], bv[4];
#pragma unroll
                for (int r = 0; r < 4; r++)
                    av[r] = *(const float4*)&sK[(t_hi + 16 * r) * SKT + d];
#pragma unroll
                for (int c = 0; c < 4; c++)
                    bv[c] = *(const float4*)&sK[(t_lo + 16 * c) * SKT + d];
#pragma unroll
                for (int r = 0; r < 4; r++)
#pragma unroll
                    for (int c = 0; c < 4; c++) acc[r][c] += dot4(av[r], bv[c]);
            }
#pragma unroll
            for (int r = 0; r < 4; r++) {
                int i = t_hi + 16 * r;
#pragma unroll
                for (int c = 0; c < 4; c++) {
                    int j = t_lo + 16 * c;
                    float val;
                    if (j < i) val = sbet[i] * expf(slg[i] - slg[j]) * acc[r][c];
                    else val = (i == j) ? 1.f : 0.f;
                    sA[i * SAT + j] = val;
                }
            }
        }
        __syncthreads();

        // ---- T = A^{-1}: column-parallel forward substitution ----
        if (tid < 64) {
            const int j = tid;
            for (int i = 0; i < 64; i++) {
                float s;
                if (i < j) s = 0.f;
                else if (i == j) s = 1.f;
                else {
                    s = 0.f;
                    for (int m = j; m < i; m++) s -= sA[i * SAT + m] * sT[m * SAT + j];
                }
                sT[i * SAT + j] = s;
            }
        }
        __syncthreads();

        // ---- P = beta_i * (V - gamma_i * K @ S^T) ----
        {
            float acc[4][2];
#pragma unroll
            for (int r = 0; r < 4; r++) { acc[r][0] = 0.f; acc[r][1] = 0.f; }
            for (int d = 0; d < 128; d += 4) {
                float4 av[4], bv[2];
#pragma unroll
                for (int r = 0; r < 4; r++)
                    av[r] = *(const float4*)&sK[(t_hi + 16 * r) * SKT + d];
                bv[0] = *(const float4*)&sS[t_lo * SKT + d];
                bv[1] = *(const float4*)&sS[(t_lo + 16) * SKT + d];
#pragma unroll
                for (int r = 0; r < 4; r++) {
                    acc[r][0] += dot4(av[r], bv[0]);
                    acc[r][1] += dot4(av[r], bv[1]);
                }
            }
#pragma unroll
            for (int r = 0; r < 4; r++) {
                int i = t_hi + 16 * r;
#pragma unroll
                for (int c = 0; c < 2; c++) {
                    int dv = t_lo + 16 * c;
                    sP[i * SVT + dv] = sbet[i] * (sV[i * SVT + dv] - sgam[i] * acc[r][c]);
                }
            }
        }
        __syncthreads();

        // ---- mid = T @ P ----
        {
            float acc[4][2];
#pragma unroll
            for (int r = 0; r < 4; r++) { acc[r][0] = 0.f; acc[r][1] = 0.f; }
            for (int m = 0; m < 64; m++) {
                float b0 = sP[m * SVT + t_lo];
                float b1 = sP[m * SVT + t_lo + 16];
#pragma unroll
                for (int r = 0; r < 4; r++) {
                    float a = sT[(t_hi + 16 * r) * SAT + m];
                    acc[r][0] += a * b0;
                    acc[r][1] += a * b1;
                }
            }
#pragma unroll
            for (int r = 0; r < 4; r++) {
                int i = t_hi + 16 * r;
                sMid[i * SVT + t_lo] = acc[r][0];
                sMid[i * SVT + t_lo + 16] = acc[r][1];
            }
        }
        __syncthreads();

        // ---- attn = (Q@K^T) * exp(lg_i - lg_j), j <= i (overwrite sA) ----
        {
            float acc[4][4];
#pragma unroll
            for (int r = 0; r < 4; r++)
#pragma unroll
                for (int c = 0; c < 4; c++) acc[r][c] = 0.f;
            for (int d = 0; d < 128; d += 4) {
                float4 av[4], bv[4];
#pragma unroll
                for (int r = 0; r < 4; r++)
                    av[r] = *(const float4*)&sQ[(t_hi + 16 * r) * SKT + d];
#pragma unroll
                for (int c = 0; c < 4; c++)
                    bv[c] = *(const float4*)&sK[(t_lo + 16 * c) * SKT + d];
#pragma unroll
                for (int r = 0; r < 4; r++)
#pragma unroll
                    for (int c = 0; c < 4; c++) acc[r][c] += dot4(av[r], bv[c]);
            }
#pragma unroll
            for (int r = 0; r < 4; r++) {
                int i = t_hi + 16 * r;
#pragma unroll
                for (int c = 0; c < 4; c++) {
                    int j = t_lo + 16 * c;
                    float val = (j <= i) ? expf(slg[i] - slg[j]) * acc[r][c] : 0.f;
                    sA[i * SAT + j] = val;
                }
            }
        }
        __syncthreads();

        // ---- O = gamma_i * (Q @ S^T) + attn @ mid ----
        {
            float acc1[4][2], acc2[4][2];
#pragma unroll
            for (int r = 0; r < 4; r++) {
                acc1[r][0] = acc1[r][1] = 0.f;
                acc2[r][0] = acc2[r][1] = 0.f;
            }
            for (int d = 0; d < 128; d += 4) {
                float4 av[4], bv[2];
#pragma unroll
                for (int r = 0; r < 4; r++)
                    av[r] = *(const float4*)&sQ[(t_hi + 16 * r) * SKT + d];
                bv[0] = *(const float4*)&sS[t_lo * SKT + d];
                bv[1] = *(const float4*)&sS[(t_lo + 16) * SKT + d];
#pragma unroll
                for (int r = 0; r < 4; r++) {
                    acc1[r][0] += dot4(av[r], bv[0]);
                    acc1[r][1] += dot4(av[r], bv[1]);
                }
            }
            for (int j = 0; j < 64; j++) {
                float b0 = sMid[j * SVT + t_lo];
                float b1 = sMid[j * SVT + t_lo + 16];
#pragma unroll
                for (int r = 0; r < 4; r++) {
                    float a = sA[(t_hi + 16 * r) * SAT + j];
                    acc2[r][0] += a * b0;
                    acc2[r][1] += a * b1;
                }
            }
#pragma unroll
            for (int r = 0; r < 4; r++) {
                int i = t_hi + 16 * r;
                float g = sgam[i];
                size_t go = (((size_t)(b * Lq + l0 + i)) * Hq + h) * Dh + dv0;
                o[go + t_lo] = g * acc1[r][0] + acc2[r][0];
                o[go + t_lo + 16] = g * acc1[r][1] + acc2[r][1];
            }
        }
        __syncthreads();

        // ---- S = gammaC * S + (mid_i * gCr_i)^T @ K ----
        {
            const int dkb = t_lo * 8;
            float acc[2][8];
#pragma unroll
            for (int r = 0; r < 2; r++)
#pragma unroll
                for (int c = 0; c < 8; c++) acc[r][c] = 0.f;
            for (int i = 0; i < 64; i++) {
                float gc = sgCr[i];
                float a0 = sMid[i * SVT + t_hi] * gc;
                float a1 = sMid[i * SVT + t_hi + 16] * gc;
                float4 k0 = *(const float4*)&sK[i * SKT + dkb];
                float4 k1 = *(const float4*)&sK[i * SKT + dkb + 4];
                acc[0][0] += a0 * k0.x; acc[0][1] += a0 * k0.y;
                acc[0][2] += a0 * k0.z; acc[0][3] += a0 * k0.w;
                acc[0][4] += a0 * k1.x; acc[0][5] += a0 * k1.y;
                acc[0][6] += a0 * k1.z; acc[0][7] += a0 * k1.w;
                acc[1][0] += a1 * k0.x; acc[1][1] += a1 * k0.y;
                acc[1][2] += a1 * k0.z; acc[1][3] += a1 * k0.w;
                acc[1][4] += a1 * k1.x; acc[1][5] += a1 * k1.y;
                acc[1][6] += a1 * k1.z; acc[1][7] += a1 * k1.w;
            }
#pragma unroll
            for (int r = 0; r < 2; r++) {
                int dv = t_hi + 16 * r;
#pragma unroll
                for (int c = 0; c < 8; c++) {
                    float* p = &sS[dv * SKT + dkb + c];
                    *p = gammaC * *p + acc[r][c];
                }
            }
        }
        __syncthreads();
    }

    // write final state slice
    for (int idx = tid; idx < 32 * 128; idx += 256) {
        int dv = idx >> 7, dk = idx & 127;
        Sout[((size_t)bh * 128 + dv0 + dv) * 128 + dk] = sS[dv * SKT + dk];
    }
}

// ---------------- RMSNorm + gate (silu) ----------------
__global__ void gate_kernel(const float* __restrict__ o, const float* __restrict__ gate,
                            const float* __restrict__ norm_w, float* __restrict__ og)
{
    const size_t base = (size_t)blockIdx.x * Dh + threadIdx.x;
    float ov = o[base];
    float s = ov * ov;
#pragma unroll
    for (int off = 16; off > 0; off >>= 1) s += __shfl_xor_sync(0xffffffffu, s, off);
    __shared__ float sh[4];
    const int wid = threadIdx.x >> 5;
    if ((threadIdx.x & 31) == 0) sh[wid] = s;
    __syncthreads();
    float mean = (sh[0] + sh[1] + sh[2] + sh[3]) * (1.f / 128.f);
    float rs = rsqrtf(mean + EPSq);
    float gv = gate[base];
    float sig = gv / (1.f + expf(-gv));
    og[base] = ov * rs * norm_w[threadIdx.x] * sig;
}

// ---------------- launch ----------------
extern "C" void kernel_launch(void* const* d_in, const int* in_sizes, int n_in,
                              void* d_out, int out_size)
{
    const float* x = (const float*)d_in[0];
    const float* Wq = (const float*)d_in[1];
    const float* Wk = (const float*)d_in[2];
    const float* Wv = (const float*)d_in[3];
    const float* Wb = (const float*)d_in[4];
    const float* Wa = (const float*)d_in[5];
    const float* A_log = (const float*)d_in[6];
    const float* dt_bias = (const float*)d_in[7];
    const float* conv_q = (const float*)d_in[8];
    const float* conv_k = (const float*)d_in[9];
    const float* conv_v = (const float*)d_in[10];
    const float* Wg = (const float*)d_in[11];
    const float* norm_w = (const float*)d_in[12];
    const float* Wo = (const float*)d_in[13];
    const float* S0 = (const float*)d_in[14];

    float* out = (float*)d_out;
    float* Sout = out + (size_t)BLD;

    float *projq, *projk, *projv, *projg, *qn, *kn, *vn, *beta, *gdec;
    __nv_bfloat16 *xs, *ws;
    cudaGetSymbolAddress((void**)&projq, g_projq);
    cudaGetSymbolAddress((void**)&projk, g_projk);
    cudaGetSymbolAddress((void**)&projv, g_projv);
    cudaGetSymbolAddress((void**)&projg, g_projg);
    cudaGetSymbolAddress((void**)&qn, g_qn);
    cudaGetSymbolAddress((void**)&kn, g_kn);
    cudaGetSymbolAddress((void**)&vn, g_vn);
    cudaGetSymbolAddress((void**)&beta, g_beta);
    cudaGetSymbolAddress((void**)&gdec, g_gdec);
    cudaGetSymbolAddress((void**)&xs, g_xs);
    cudaGetSymbolAddress((void**)&ws, g_ws);

    __nv_bfloat16* wsq = ws;
    __nv_bfloat16* wsk = ws + 1 * (size_t)Dq * KS;
    __nv_bfloat16* wsv = ws + 2 * (size_t)Dq * KS;
    __nv_bfloat16* wsg = ws + 3 * (size_t)Dq * KS;
    __nv_bfloat16* wso = ws + 4 * (size_t)Dq * KS;

    float* obuf = projk;
    float* ogbuf = projq;

    cudaFuncSetAttribute(scan_kernel, cudaFuncAttributeMaxDynamicSharedMemorySize,
                         SCAN_SMEM_BYTES);
    cudaFuncSetAttribute(hmma_gemm, cudaFuncAttributeMaxDynamicSharedMemorySize,
                         GEMM_SMEM_BYTES);

    // split conversions
    split_bf16<<<BLD / 256, 256>>>(x, xs, 0);
    split_bf16<<<(Dq * Dq) / 256, 256>>>(Wq, wsq, 1);
    split_bf16<<<(Dq * Dq) / 256, 256>>>(Wk, wsk, 1);
    split_bf16<<<(Dq * Dq) / 256, 256>>>(Wv, wsv, 1);
    split_bf16<<<(Dq * Dq) / 256, 256>>>(Wg, wsg, 1);
    split_bf16<<<(Dq * Dq) / 256, 256>>>(Wo, wso, 1);

    dim3 ggrid(Dq / 128, BLq / 128);   // (16, 64)

    hmma_gemm<<<ggrid, 256, GEMM_SMEM_BYTES>>>(xs, wsq, projq);
    hmma_gemm<<<ggrid, 256, GEMM_SMEM_BYTES>>>(xs, wsk, projk);
    hmma_gemm<<<ggrid, 256, GEMM_SMEM_BYTES>>>(xs, wsv, projv);
    hmma_gemm<<<ggrid, 256, GEMM_SMEM_BYTES>>>(xs, wsg, projg);

    betag_kernel<<<BLq, 512>>>(x, Wb, Wa, A_log, dt_bias, beta, gdec);

    conv_kernel<<<BLq * Hq, 128>>>(projq, projk, projv, conv_q, conv_k, conv_v,
                                   qn, kn, vn);

    scan_kernel<<<Bq * Hq * 4, 256, SCAN_SMEM_BYTES>>>(qn, kn, vn, beta, gdec, S0,
                                                       obuf, Sout);

    gate_kernel<<<BLq * Hq, 128>>>(obuf, projg, norm_w, ogbuf);

    split_bf16<<<BLD / 256, 256>>>(ogbuf, xs, 0);
    hmma_gemm<<<ggrid, 256, GEMM_SMEM_BYTES>>>(xs, wso, out);
}

// round 8
// speedup vs baseline: 3.6514x; 1.3464x over previous
#include <cuda_runtime.h>
#include <cuda_bf16.h>
#include <cstdint>
#include <cstddef>

#define Bq 2
#define Lq 4096
#define Dq 2048
#define Hq 16
#define Dh 128
#define Cq 64
#define Nq (Lq / Cq)
#define KW 4
#define BLq (Bq * Lq)
#define EPSq 1e-5f

#define NCq 96                // 3 * 32 K-chunks of 64

// ---------------- device scratch buffers ----------------
#define BLD (BLq * Dq)         // 16,777,216
#define BHL (Bq * Hq * Lq)     // 131,072
#define WROWS (5 * Dq)         // 5 weight matrices stacked

__device__ float g_proj[(size_t)BLq * 4 * Dq];   // merged q|k|v|g projections
__device__ float g_obuf[BLD];
__device__ float g_qn[BLD];
__device__ float g_kn[BLD];
__device__ float g_vn[BLD];
__device__ float g_beta[BHL];
__device__ float g_gdec[BHL];

__device__ __nv_bfloat16 g_xhi[(size_t)BLq * Dq];
__device__ __nv_bfloat16 g_xlo[(size_t)BLq * Dq];
__device__ __nv_bfloat16 g_whi[(size_t)WROWS * Dq];
__device__ __nv_bfloat16 g_wlo[(size_t)WROWS * Dq];

// ================= helpers =================
__device__ __forceinline__ uint32_t smem_u32(const void* p) {
    uint32_t a;
    asm("{ .reg .u64 t; cvta.to.shared.u64 t, %1; cvt.u32.u64 %0, t; }" : "=r"(a) : "l"(p));
    return a;
}
#define SWZ(x) ((x) ^ (((x) >> 3) & 0x70))

__device__ __forceinline__ void cp16(uint32_t dst, const void* src) {
    asm volatile("cp.async.cg.shared.global [%0], [%1], 16;" :: "r"(dst), "l"(src));
}
__device__ __forceinline__ void ldsm_x4(uint32_t& r0, uint32_t& r1, uint32_t& r2,
                                        uint32_t& r3, uint32_t a) {
    asm volatile("ldmatrix.sync.aligned.m8n8.x4.shared.b16 {%0,%1,%2,%3}, [%4];"
                 : "=r"(r0), "=r"(r1), "=r"(r2), "=r"(r3) : "r"(a));
}
__device__ __forceinline__ void ldsm_x2(uint32_t& r0, uint32_t& r1, uint32_t a) {
    asm volatile("ldmatrix.sync.aligned.m8n8.x2.shared.b16 {%0,%1}, [%2];"
                 : "=r"(r0), "=r"(r1) : "r"(a));
}
__device__ __forceinline__ void mma16816(float* d, const uint32_t* a, const uint32_t* b) {
    asm volatile("mma.sync.aligned.m16n8k16.row.col.f32.bf16.bf16.f32 "
                 "{%0,%1,%2,%3}, {%4,%5,%6,%7}, {%8,%9}, {%0,%1,%2,%3};"
                 : "+f"(d[0]), "+f"(d[1]), "+f"(d[2]), "+f"(d[3])
                 : "r"(a[0]), "r"(a[1]), "r"(a[2]), "r"(a[3]), "r"(b[0]), "r"(b[1]));
}
__device__ __forceinline__ float dot4(float4 a, float4 b) {
    return a.x * b.x + a.y * b.y + a.z * b.z + a.w * b.w;
}

// ---------------- split: fp32 [rows,2048] -> bf16 hi + lo ----------------
__global__ void split2_bf16(const float* __restrict__ in, __nv_bfloat16* __restrict__ hi,
                            __nv_bfloat16* __restrict__ lo)
{
    size_t idx = (size_t)blockIdx.x * blockDim.x + threadIdx.x;
    float a = in[idx];
    __nv_bfloat16 h = __float2bfloat16_rn(a);
    hi[idx] = h;
    lo[idx] = __float2bfloat16_rn(a - __bfloat162float(h));
}

// ---------------- HMMA GEMM with split-3 chunk routing --------------------
// C[M, ldc(=N)] = A[M,2048] * B[N,2048]^T in fp32-ish precision:
// chunks 0-31: Ahi*Bhi, 32-63: Ahi*Blo, 64-95: Alo*Bhi.
#define STAGE_B 32768
#define GEMM_SMEM_BYTES (3 * STAGE_B)

__global__ __launch_bounds__(256, 2)
void hmma_gemm(const __nv_bfloat16* __restrict__ Ahi, const __nv_bfloat16* __restrict__ Alo,
               const __nv_bfloat16* __restrict__ Bhi, const __nv_bfloat16* __restrict__ Blo,
               float* __restrict__ C, int ldc)
{
    extern __shared__ __align__(128) char smem[];
    const uint32_t sb = smem_u32(smem);
    const int tid = threadIdx.x;
    const int warp = tid >> 5, lane = tid & 31;
    const int wm = warp & 1, wn = warp >> 1;
    const int bm = blockIdx.y * 128, bn = blockIdx.x * 128;

    float acc[4][4][4];
#pragma unroll
    for (int i = 0; i < 4; i++)
#pragma unroll
        for (int j = 0; j < 4; j++)
#pragma unroll
            for (int r = 0; r < 4; r++) acc[i][j][r] = 0.f;

    const int lrow = tid >> 3;
    const int lseg = tid & 7;
    const uint32_t loff = SWZ(lrow * 128 + lseg * 16);

#define LOAD_STAGE(s, kc) do { \
        int _reg = (kc) >> 5; \
        int _k0 = ((kc) & 31) * 64; \
        const __nv_bfloat16* _Aa = (_reg == 2) ? Alo : Ahi; \
        const __nv_bfloat16* _Bb = (_reg == 1) ? Blo : Bhi; \
        uint32_t _as = sb + (s) * STAGE_B; \
        uint32_t _bs = _as + 16384; \
        const __nv_bfloat16* _ap = _Aa + (size_t)(bm + lrow) * Dq + _k0 + lseg * 8; \
        const __nv_bfloat16* _bp = _Bb + (size_t)(bn + lrow) * Dq + _k0 + lseg * 8; \
        _Pragma("unroll") \
        for (int _i = 0; _i < 4; _i++) { \
            cp16(_as + loff + _i * 4096, _ap + (size_t)_i * 32 * Dq); \
            cp16(_bs + loff + _i * 4096, _bp + (size_t)_i * 32 * Dq); \
        } \
        asm volatile("cp.async.commit_group;" ::: "memory"); \
    } while (0)

    const int aq = lane >> 3;
    const int am = (lane & 7) + (aq & 1) * 8;
    const int akb = (aq >> 1) * 8;
    const int bl = lane & 15;
    const int bn8 = bl & 7;
    const int bkb = (bl >> 3) * 8;

    LOAD_STAGE(0, 0);
    LOAD_STAGE(1, 1);

    for (int c = 0; c < NCq; c++) {
        if (c == NCq - 1) {
            asm volatile("cp.async.wait_group 0;" ::: "memory");
        } else {
            asm volatile("cp.async.wait_group 1;" ::: "memory");
        }
        __syncthreads();
        if (c + 2 < NCq) LOAD_STAGE((c + 2) % 3, c + 2);

        const uint32_t As = sb + (c % 3) * STAGE_B;
        const uint32_t Bs = As + 16384;
#pragma unroll
        for (int ks = 0; ks < 4; ks++) {
            const int k0 = ks * 16;
            uint32_t af[4][4];
#pragma unroll
            for (int mt = 0; mt < 4; mt++) {
                int m = wm * 64 + mt * 16 + am;
                ldsm_x4(af[mt][0], af[mt][1], af[mt][2], af[mt][3],
                        As + SWZ(m * 128 + (k0 + akb) * 2));
            }
            uint32_t bf[4][2];
#pragma unroll
            for (int nt = 0; nt < 4; nt++) {
                int n = wn * 32 + nt * 8 + bn8;
                ldsm_x2(bf[nt][0], bf[nt][1],
                        Bs + SWZ(n * 128 + (k0 + bkb) * 2));
            }
#pragma unroll
            for (int mt = 0; mt < 4; mt++)
#pragma unroll
                for (int nt = 0; nt < 4; nt++)
                    mma16816(acc[mt][nt], af[mt], bf[nt]);
        }
    }

    const int r0 = bm + wm * 64 + (lane >> 2);
    const int c0 = bn + wn * 32 + (lane & 3) * 2;
#pragma unroll
    for (int mt = 0; mt < 4; mt++) {
#pragma unroll
        for (int nt = 0; nt < 4; nt++) {
            float2* p0 = (float2*)(C + (size_t)(r0 + mt * 16) * ldc + c0 + nt * 8);
            float2* p1 = (float2*)(C + (size_t)(r0 + mt * 16 + 8) * ldc + c0 + nt * 8);
            *p0 = make_float2(acc[mt][nt][0], acc[mt][nt][1]);
            *p1 = make_float2(acc[mt][nt][2], acc[mt][nt][3]);
        }
    }
}

// ---------------- beta / g kernel ----------------
__global__ void betag_kernel(const float* __restrict__ x,
                             const float* __restrict__ Wb,
                             const float* __restrict__ Wa,
                             const float* __restrict__ A_log,
                             const float* __restrict__ dt_bias,
                             float* __restrict__ beta,
                             float* __restrict__ gdec)
{
    const int bl = blockIdx.x;
    const int h = threadIdx.x >> 5;
    const int lane = threadIdx.x & 31;
    const float* xr = x + (size_t)bl * Dq;
    const float* wb = Wb + (size_t)h * Dq;
    const float* wa = Wa + (size_t)h * Dq;
    float sb = 0.f, sa = 0.f;
    for (int i = lane; i < Dq; i += 32) {
        float xv = xr[i];
        sb += xv * wb[i];
        sa += xv * wa[i];
    }
#pragma unroll
    for (int off = 16; off > 0; off >>= 1) {
        sb += __shfl_down_sync(0xffffffffu, sb, off);
        sa += __shfl_down_sync(0xffffffffu, sa, off);
    }
    if (lane == 0) {
        const int b = bl / Lq, l = bl % Lq;
        float bet = 1.f / (1.f + expf(-sb));
        float z = sa + dt_bias[h];
        float sp = (z > 15.f) ? z : log1pf(expf(z));
        float g = -expf(A_log[h]) * sp;
        size_t o = ((size_t)(b * Hq + h)) * Lq + l;
        beta[o] = bet;
        gdec[o] = g;
    }
}

// ---------------- causal dwconv + silu + l2 norm (reads merged proj) ----------
__global__ void conv_kernel(const float* __restrict__ proj,
                            const float* __restrict__ wq, const float* __restrict__ wk,
                            const float* __restrict__ wv,
                            float* __restrict__ oq, float* __restrict__ ok,
                            float* __restrict__ ov)
{
    const int blk = blockIdx.x;
    const int h = blk % Hq;
    const int bl = blk / Hq;
    const int l = bl % Lq;
    const int d = threadIdx.x;
    const int c = h * Dh + d;

    float aq = 0.f, ak = 0.f, av = 0.f;
#pragma unroll
    for (int j = 0; j < KW; j++) {
        int ll = l - (KW - 1) + j;
        if (ll >= 0) {
            size_t idx = ((size_t)(bl - l + ll)) * (4 * Dq) + c;
            aq += wq[c * KW + j] * proj[idx];
            ak += wk[c * KW + j] * proj[idx + Dq];
            av += wv[c * KW + j] * proj[idx + 2 * Dq];
        }
    }
    aq = aq / (1.f + expf(-aq));
    ak = ak / (1.f + expf(-ak));
    av = av / (1.f + expf(-av));

    float sq = aq * aq, sk = ak * ak;
#pragma unroll
    for (int off = 16; off > 0; off >>= 1) {
        sq += __shfl_xor_sync(0xffffffffu, sq, off);
        sk += __shfl_xor_sync(0xffffffffu, sk, off);
    }
    __shared__ float shq[4], shk[4];
    const int wid = threadIdx.x >> 5;
    if ((threadIdx.x & 31) == 0) { shq[wid] = sq; shk[wid] = sk; }
    __syncthreads();
    float sumq = shq[0] + shq[1] + shq[2] + shq[3];
    float sumk = shk[0] + shk[1] + shk[2] + shk[3];
    float invq = 1.f / fmaxf(sqrtf(sumq), 1e-12f);
    float invk = 1.f / fmaxf(sqrtf(sumk), 1e-12f);

    size_t base = (size_t)bl * Dq + c;
    oq[base] = aq * invq * 0.08838834764831845f;
    ok[base] = ak * invk;
    ov[base] = av;
}

// ---------------- chunked gated delta-rule scan (register-tiled) ----------------
#define SKT 132
#define SAT 68
#define SVT 36

#define SK_OFF  0
#define SQ_OFF  8448
#define SS_OFF  16896
#define SA_OFF  21120
#define SV_OFF  25472
#define SP_OFF  27776
#define SC_OFF  30080
#define SCAN_SMEM_FLOATS (SC_OFF + 320)
#define SCAN_SMEM_BYTES (SCAN_SMEM_FLOATS * 4)

__global__ __launch_bounds__(256, 1)
void scan_kernel(const float* __restrict__ q, const float* __restrict__ k,
                 const float* __restrict__ v, const float* __restrict__ beta,
                 const float* __restrict__ gdec, const float* __restrict__ S0,
                 float* __restrict__ o, float* __restrict__ Sout)
{
    extern __shared__ float sm[];
    float* sK = sm + SK_OFF;     // [64 i][SKT]
    float* sQ = sm + SQ_OFF;     // [64 i][SKT]
    float* sS = sm + SS_OFF;     // [32 dv][SKT]
    float* sA = sm + SA_OFF;     // [64][SAT]
    float* sV = sm + SV_OFF;     // [64 i][SVT]
    float* sP = sm + SP_OFF;     // [64 i][SVT]  (P, then mid in place)
    float* slg = sm + SC_OFF;
    float* sgam = slg + 64;
    float* sgCr = sgam + 64;
    float* sbet = sgCr + 64;
    float* sgg = sbet + 64;

    const int bh = blockIdx.x >> 2;
    const int grp = blockIdx.x & 3;
    const int b = bh >> 4;
    const int h = bh & 15;
    const int dv0 = grp * 32;
    const int tid = threadIdx.x;
    const int t_hi = tid >> 4;
    const int t_lo = tid & 15;

    for (int idx = tid; idx < 32 * 128; idx += 256) {
        int dv = idx >> 7, dk = idx & 127;
        sS[dv * SKT + dk] = S0[((size_t)bh * 128 + dv0 + dv) * 128 + dk];
    }

    for (int n = 0; n < Nq; n++) {
        const int l0 = n * Cq;
        for (int idx = tid; idx < 64 * 128; idx += 256) {
            int i = idx >> 7, d = idx & 127;
            size_t gi = (((size_t)(b * Lq + l0 + i)) * Hq + h) * Dh + d;
            sK[i * SKT + d] = k[gi];
            sQ[i * SKT + d] = q[gi];
        }
        for (int idx = tid; idx < 64 * 32; idx += 256) {
            int i = idx >> 5, dv = idx & 31;
            sV[i * SVT + dv] = v[(((size_t)(b * Lq + l0 + i)) * Hq + h) * Dh + dv0 + dv];
        }
        if (tid < 64) {
            sbet[tid] = beta[(size_t)bh * Lq + l0 + tid];
            sgg[tid] = gdec[(size_t)bh * Lq + l0 + tid];
        }
        __syncthreads();
        if (tid == 0) {
            float c = 0.f;
            for (int i = 0; i < 64; i++) { c += sgg[i]; slg[i] = c; }
        }
        __syncthreads();
        const float lgC = slg[63];
        if (tid < 64) {
            sgam[tid] = expf(slg[tid]);
            sgCr[tid] = expf(lgC - slg[tid]);
        }
        __syncthreads();
        const float gammaC = expf(lgC);

        // ---- A = beta_i * exp(lg_i - lg_j) * (K_i . K_j) (strict lower; diag 1) ----
        {
            float acc[4][4];
#pragma unroll
            for (int r = 0; r < 4; r++)
#pragma unroll
                for (int c = 0; c < 4; c++) acc[r][c] = 0.f;
            for (int d = 0; d < 128; d += 4) {
                float4 av[4], bv[4];
#pragma unroll
                for (int r = 0; r < 4; r++)
                    av[r] = *(const float4*)&sK[(t_hi + 16 * r) * SKT + d];
#pragma unroll
                for (int c = 0; c < 4; c++)
                    bv[c] = *(const float4*)&sK[(t_lo + 16 * c) * SKT + d];
#pragma unroll
                for (int r = 0; r < 4; r++)
#pragma unroll
                    for (int c = 0; c < 4; c++) acc[r][c] += dot4(av[r], bv[c]);
            }
#pragma unroll
            for (int r = 0; r < 4; r++) {
                int i = t_hi + 16 * r;
#pragma unroll
                for (int c = 0; c < 4; c++) {
                    int j = t_lo + 16 * c;
                    float val;
                    if (j < i) val = sbet[i] * expf(slg[i] - slg[j]) * acc[r][c];
                    else val = (i == j) ? 1.f : 0.f;
                    sA[i * SAT + j] = val;
                }
            }
        }
        __syncthreads();

        // ---- P = beta_i * (V - gamma_i * K @ S^T) ----
        {
            float acc[4][2];
#pragma unroll
            for (int r = 0; r < 4; r++) { acc[r][0] = 0.f; acc[r][1] = 0.f; }
            for (int d = 0; d < 128; d += 4) {
                float4 av[4], bv[2];
#pragma unroll
                for (int r = 0; r < 4; r++)
                    av[r] = *(const float4*)&sK[(t_hi + 16 * r) * SKT + d];
                bv[0] = *(const float4*)&sS[t_lo * SKT + d];
                bv[1] = *(const float4*)&sS[(t_lo + 16) * SKT + d];
#pragma unroll
                for (int r = 0; r < 4; r++) {
                    acc[r][0] += dot4(av[r], bv[0]);
                    acc[r][1] += dot4(av[r], bv[1]);
                }
            }
#pragma unroll
            for (int r = 0; r < 4; r++) {
                int i = t_hi + 16 * r;
#pragma unroll
                for (int c = 0; c < 2; c++) {
                    int dv = t_lo + 16 * c;
                    sP[i * SVT + dv] = sbet[i] * (sV[i * SVT + dv] - sgam[i] * acc[r][c]);
                }
            }
        }
        __syncthreads();

        // ---- solve A * mid = P in place (blocked forward substitution) ----
#pragma unroll 1
        for (int blk = 0; blk < 8; blk++) {
            const int r0 = blk * 8;
            if (tid < 32) {
                const int dv = tid;
                float vals[8];
                vals[0] = sP[r0 * SVT + dv];
#pragma unroll
                for (int r = 1; r < 8; r++) {
                    float acc = sP[(r0 + r) * SVT + dv];
#pragma unroll
                    for (int m = 0; m < 8; m++)
                        if (m < r) acc -= sA[(r0 + r) * SAT + r0 + m] * vals[m];
                    vals[r] = acc;
                }
#pragma unroll
                for (int r = 1; r < 8; r++) sP[(r0 + r) * SVT + dv] = vals[r];
            }
            __syncthreads();
            const int nrem = 64 - r0 - 8;
            if (nrem > 0) {
                for (int idx = tid; idx < nrem * 32; idx += 256) {
                    int i = r0 + 8 + (idx >> 5);
                    int dv = idx & 31;
                    float acc = sP[i * SVT + dv];
#pragma unroll
                    for (int m = 0; m < 8; m++)
                        acc -= sA[i * SAT + r0 + m] * sP[(r0 + m) * SVT + dv];
                    sP[i * SVT + dv] = acc;
                }
            }
            __syncthreads();
        }

        // ---- attn = (Q@K^T) * exp(lg_i - lg_j), j <= i (overwrite sA) ----
        {
            float acc[4][4];
#pragma unroll
            for (int r = 0; r < 4; r++)
#pragma unroll
                for (int c = 0; c < 4; c++) acc[r][c] = 0.f;
            for (int d = 0; d < 128; d += 4) {
                float4 av[4], bv[4];
#pragma unroll
                for (int r = 0; r < 4; r++)
                    av[r] = *(const float4*)&sQ[(t_hi + 16 * r) * SKT + d];
#pragma unroll
                for (int c = 0; c < 4; c++)
                    bv[c] = *(const float4*)&sK[(t_lo + 16 * c) * SKT + d];
#pragma unroll
                for (int r = 0; r < 4; r++)
#pragma unroll
                    for (int c = 0; c < 4; c++) acc[r][c] += dot4(av[r], bv[c]);
            }
#pragma unroll
            for (int r = 0; r < 4; r++) {
                int i = t_hi + 16 * r;
#pragma unroll
                for (int c = 0; c < 4; c++) {
                    int j = t_lo + 16 * c;
                    float val = (j <= i) ? expf(slg[i] - slg[j]) * acc[r][c] : 0.f;
                    sA[i * SAT + j] = val;
                }
            }
        }
        __syncthreads();

        // ---- O = gamma_i * (Q @ S^T) + attn @ mid ----
        {
            float acc1[4][2], acc2[4][2];
#pragma unroll
            for (int r = 0; r < 4; r++) {
                acc1[r][0] = acc1[r][1] = 0.f;
                acc2[r][0] = acc2[r][1] = 0.f;
            }
            for (int d = 0; d < 128; d += 4) {
                float4 av[4], bv[2];
#pragma unroll
                for (int r = 0; r < 4; r++)
                    av[r] = *(const float4*)&sQ[(t_hi + 16 * r) * SKT + d];
                bv[0] = *(const float4*)&sS[t_lo * SKT + d];
                bv[1] = *(const float4*)&sS[(t_lo + 16) * SKT + d];
#pragma unroll
                for (int r = 0; r < 4; r++) {
                    acc1[r][0] += dot4(av[r], bv[0]);
                    acc1[r][1] += dot4(av[r], bv[1]);
                }
            }
            for (int j = 0; j < 64; j++) {
                float b0 = sP[j * SVT + t_lo];
                float b1 = sP[j * SVT + t_lo + 16];
#pragma unroll
                for (int r = 0; r < 4; r++) {
                    float a = sA[(t_hi + 16 * r) * SAT + j];
                    acc2[r][0] += a * b0;
                    acc2[r][1] += a * b1;
                }
            }
#pragma unroll
            for (int r = 0; r < 4; r++) {
                int i = t_hi + 16 * r;
                float g = sgam[i];
                size_t go = (((size_t)(b * Lq + l0 + i)) * Hq + h) * Dh + dv0;
                o[go + t_lo] = g * acc1[r][0] + acc2[r][0];
                o[go + t_lo + 16] = g * acc1[r][1] + acc2[r][1];
            }
        }
        __syncthreads();

        // ---- S = gammaC * S + (mid_i * gCr_i)^T @ K ----
        {
            const int dkb = t_lo * 8;
            float acc[2][8];
#pragma unroll
            for (int r = 0; r < 2; r++)
#pragma unroll
                for (int c = 0; c < 8; c++) acc[r][c] = 0.f;
            for (int i = 0; i < 64; i++) {
                float gc = sgCr[i];
                float a0 = sP[i * SVT + t_hi] * gc;
                float a1 = sP[i * SVT + t_hi + 16] * gc;
                float4 k0 = *(const float4*)&sK[i * SKT + dkb];
                float4 k1 = *(const float4*)&sK[i * SKT + dkb + 4];
                acc[0][0] += a0 * k0.x; acc[0][1] += a0 * k0.y;
                acc[0][2] += a0 * k0.z; acc[0][3] += a0 * k0.w;
                acc[0][4] += a0 * k1.x; acc[0][5] += a0 * k1.y;
                acc[0][6] += a0 * k1.z; acc[0][7] += a0 * k1.w;
                acc[1][0] += a1 * k0.x; acc[1][1] += a1 * k0.y;
                acc[1][2] += a1 * k0.z; acc[1][3] += a1 * k0.w;
                acc[1][4] += a1 * k1.x; acc[1][5] += a1 * k1.y;
                acc[1][6] += a1 * k1.z; acc[1][7] += a1 * k1.w;
            }
#pragma unroll
            for (int r = 0; r < 2; r++) {
                int dv = t_hi + 16 * r;
#pragma unroll
                for (int c = 0; c < 8; c++) {
                    float* p = &sS[dv * SKT + dkb + c];
                    *p = gammaC * *p + acc[r][c];
                }
            }
        }
        __syncthreads();
    }

    for (int idx = tid; idx < 32 * 128; idx += 256) {
        int dv = idx >> 7, dk = idx & 127;
        Sout[((size_t)bh * 128 + dv0 + dv) * 128 + dk] = sS[dv * SKT + dk];
    }
}

// ---------------- RMSNorm + gate (silu) -> bf16 hi/lo directly ----------------
__global__ void gate_kernel(const float* __restrict__ o, const float* __restrict__ proj,
                            const float* __restrict__ norm_w,
                            __nv_bfloat16* __restrict__ ohi, __nv_bfloat16* __restrict__ olo)
{
    const size_t base = (size_t)blockIdx.x * Dh + threadIdx.x;
    const size_t row = blockIdx.x >> 4;
    const size_t inner = (size_t)(blockIdx.x & 15) * Dh + threadIdx.x;
    float ov = o[base];
    float s = ov * ov;
#pragma unroll
    for (int off = 16; off > 0; off >>= 1) s += __shfl_xor_sync(0xffffffffu, s, off);
    __shared__ float sh[4];
    const int wid = threadIdx.x >> 5;
    if ((threadIdx.x & 31) == 0) sh[wid] = s;
    __syncthreads();
    float mean = (sh[0] + sh[1] + sh[2] + sh[3]) * (1.f / 128.f);
    float rs = rsqrtf(mean + EPSq);
    float gv = proj[row * (4 * Dq) + 3 * Dq + inner];
    float sig = gv / (1.f + expf(-gv));
    float val = ov * rs * norm_w[threadIdx.x] * sig;
    __nv_bfloat16 hi = __float2bfloat16_rn(val);
    ohi[base] = hi;
    olo[base] = __float2bfloat16_rn(val - __bfloat162float(hi));
}

// ---------------- launch ----------------
extern "C" void kernel_launch(void* const* d_in, const int* in_sizes, int n_in,
                              void* d_out, int out_size)
{
    const float* x = (const float*)d_in[0];
    const float* Wq = (const float*)d_in[1];
    const float* Wk = (const float*)d_in[2];
    const float* Wv = (const float*)d_in[3];
    const float* Wb = (const float*)d_in[4];
    const float* Wa = (const float*)d_in[5];
    const float* A_log = (const float*)d_in[6];
    const float* dt_bias = (const float*)d_in[7];
    const float* conv_q = (const float*)d_in[8];
    const float* conv_k = (const float*)d_in[9];
    const float* conv_v = (const float*)d_in[10];
    const float* Wg = (const float*)d_in[11];
    const float* norm_w = (const float*)d_in[12];
    const float* Wo = (const float*)d_in[13];
    const float* S0 = (const float*)d_in[14];

    float* out = (float*)d_out;
    float* Sout = out + (size_t)BLD;

    float *proj, *obuf, *qn, *kn, *vn, *beta, *gdec;
    __nv_bfloat16 *xhi, *xlo, *whi, *wlo;
    cudaGetSymbolAddress((void**)&proj, g_proj);
    cudaGetSymbolAddress((void**)&obuf, g_obuf);
    cudaGetSymbolAddress((void**)&qn, g_qn);
    cudaGetSymbolAddress((void**)&kn, g_kn);
    cudaGetSymbolAddress((void**)&vn, g_vn);
    cudaGetSymbolAddress((void**)&beta, g_beta);
    cudaGetSymbolAddress((void**)&gdec, g_gdec);
    cudaGetSymbolAddress((void**)&xhi, g_xhi);
    cudaGetSymbolAddress((void**)&xlo, g_xlo);
    cudaGetSymbolAddress((void**)&whi, g_whi);
    cudaGetSymbolAddress((void**)&wlo, g_wlo);

    cudaFuncSetAttribute(scan_kernel, cudaFuncAttributeMaxDynamicSharedMemorySize,
                         SCAN_SMEM_BYTES);
    cudaFuncSetAttribute(hmma_gemm, cudaFuncAttributeMaxDynamicSharedMemorySize,
                         GEMM_SMEM_BYTES);

    const size_t WSZ = (size_t)Dq * Dq;   // one weight matrix

    // 0-4: splits (x, Wq, Wk, Wv, Wg)
    split2_bf16<<<BLD / 256, 256>>>(x, xhi, xlo);
    split2_bf16<<<WSZ / 256, 256>>>(Wq, whi, wlo);
    split2_bf16<<<WSZ / 256, 256>>>(Wk, whi + WSZ, wlo + WSZ);
    split2_bf16<<<WSZ / 256, 256>>>(Wv, whi + 2 * WSZ, wlo + 2 * WSZ);
    split2_bf16<<<WSZ / 256, 256>>>(Wg, whi + 3 * WSZ, wlo + 3 * WSZ);

    // 5: merged projection GEMM: [8192, 2048] x [8192, 2048]^T -> [8192, 8192]
    dim3 pgrid(4 * Dq / 128, BLq / 128);   // (64, 64)
    hmma_gemm<<<pgrid, 256, GEMM_SMEM_BYTES>>>(xhi, xlo, whi, wlo, proj, 4 * Dq);

    // remaining prep
    split2_bf16<<<WSZ / 256, 256>>>(Wo, whi + 4 * WSZ, wlo + 4 * WSZ);
    betag_kernel<<<BLq, 512>>>(x, Wb, Wa, A_log, dt_bias, beta, gdec);

    conv_kernel<<<BLq * Hq, 128>>>(proj, conv_q, conv_k, conv_v, qn, kn, vn);

    scan_kernel<<<Bq * Hq * 4, 256, SCAN_SMEM_BYTES>>>(qn, kn, vn, beta, gdec, S0,
                                                       obuf, Sout);

    gate_kernel<<<BLq * Hq, 128>>>(obuf, proj, norm_w, xhi, xlo);

    // output projection
    dim3 ogrid(Dq / 128, BLq / 128);       // (16, 64)
    hmma_gemm<<<ogrid, 256, GEMM_SMEM_BYTES>>>(xhi, xlo, whi + 4 * WSZ, wlo + 4 * WSZ,
                                               out, Dq);
}

// round 9
// speedup vs baseline: 4.5375x; 1.2427x over previous
#include <cuda_runtime.h>
#include <cuda_bf16.h>
#include <cuda_fp16.h>
#include <cstdint>
#include <cstddef>

#define Bq 2
#define Lq 4096
#define Dq 2048
#define Hq 16
#define Dh 128
#define Cq 64
#define Nq (Lq / Cq)
#define KW 4
#define BLq (Bq * Lq)
#define EPSq 1e-5f

#define GNC 64                // 2 * 32 K-chunks of 64 (fp16 split-2)

// ---------------- device scratch buffers ----------------
#define BLD (BLq * Dq)         // 16,777,216
#define BHL (Bq * Hq * Lq)     // 131,072
#define WROWS (5 * Dq)

__device__ float g_proj[(size_t)BLq * 4 * Dq];   // merged q|k|v|g projections
__device__ float g_obuf[BLD];
__device__ float g_qn[BLD];
__device__ float g_kn[BLD];
__device__ float g_vn[BLD];
__device__ float g_beta[BHL];
__device__ float g_gdec[BHL];

__device__ __half g_xh[(size_t)BLq * Dq];        // fp16 activations (x, then gated o)
__device__ __half g_whi[(size_t)WROWS * Dq];
__device__ __half g_wlo[(size_t)WROWS * Dq];

// ================= helpers =================
__device__ __forceinline__ uint32_t smem_u32(const void* p) {
    uint32_t a;
    asm("{ .reg .u64 t; cvta.to.shared.u64 t, %1; cvt.u32.u64 %0, t; }" : "=r"(a) : "l"(p));
    return a;
}
#define SWZ(x) ((x) ^ (((x) >> 3) & 0x70))

__device__ __forceinline__ void cp16(uint32_t dst, const void* src) {
    asm volatile("cp.async.cg.shared.global [%0], [%1], 16;" :: "r"(dst), "l"(src));
}
__device__ __forceinline__ void ldsm_x4(uint32_t& r0, uint32_t& r1, uint32_t& r2,
                                        uint32_t& r3, uint32_t a) {
    asm volatile("ldmatrix.sync.aligned.m8n8.x4.shared.b16 {%0,%1,%2,%3}, [%4];"
                 : "=r"(r0), "=r"(r1), "=r"(r2), "=r"(r3) : "r"(a));
}
__device__ __forceinline__ void ldsm_x2(uint32_t& r0, uint32_t& r1, uint32_t a) {
    asm volatile("ldmatrix.sync.aligned.m8n8.x2.shared.b16 {%0,%1}, [%2];"
                 : "=r"(r0), "=r"(r1) : "r"(a));
}
__device__ __forceinline__ void mma16816(float* d, const uint32_t* a, const uint32_t* b) {
    asm volatile("mma.sync.aligned.m16n8k16.row.col.f32.f16.f16.f32 "
                 "{%0,%1,%2,%3}, {%4,%5,%6,%7}, {%8,%9}, {%0,%1,%2,%3};"
                 : "+f"(d[0]), "+f"(d[1]), "+f"(d[2]), "+f"(d[3])
                 : "r"(a[0]), "r"(a[1]), "r"(a[2]), "r"(a[3]), "r"(b[0]), "r"(b[1]));
}
__device__ __forceinline__ float dot4(float4 a, float4 b) {
    return a.x * b.x + a.y * b.y + a.z * b.z + a.w * b.w;
}

// ---------------- fp32 -> fp16 cast (activations) ----------------
__global__ void cast_f16(const float* __restrict__ in, __half* __restrict__ out)
{
    size_t idx = (size_t)blockIdx.x * blockDim.x + threadIdx.x;
    out[idx] = __float2half_rn(in[idx]);
}

// ---------------- fp32 -> fp16 hi + lo (weights, ~22-bit representation) -------
__global__ void split2_f16(const float* __restrict__ in, __half* __restrict__ hi,
                           __half* __restrict__ lo)
{
    size_t idx = (size_t)blockIdx.x * blockDim.x + threadIdx.x;
    float a = in[idx];
    __half h = __float2half_rn(a);
    hi[idx] = h;
    lo[idx] = __float2half_rn(a - __half2float(h));
}

// ---------------- HMMA GEMM, fp16 split-2 chunk routing --------------------
// C[M, ldc(=N)] = A[M,2048](fp16) * (Whi + Wlo)[N,2048]^T
// chunks 0-31: A*Whi; chunks 32-63: A*Wlo.
#define STAGE_B 32768
#define GEMM_SMEM_BYTES (3 * STAGE_B)

__global__ __launch_bounds__(256, 2)
void hmma_gemm(const __half* __restrict__ A,
               const __half* __restrict__ Bhi, const __half* __restrict__ Blo,
               float* __restrict__ C, int ldc)
{
    extern __shared__ __align__(128) char smem[];
    const uint32_t sb = smem_u32(smem);
    const int tid = threadIdx.x;
    const int warp = tid >> 5, lane = tid & 31;
    const int wm = warp & 1, wn = warp >> 1;
    const int bm = blockIdx.y * 128, bn = blockIdx.x * 128;

    float acc[4][4][4];
#pragma unroll
    for (int i = 0; i < 4; i++)
#pragma unroll
        for (int j = 0; j < 4; j++)
#pragma unroll
            for (int r = 0; r < 4; r++) acc[i][j][r] = 0.f;

    const int lrow = tid >> 3;
    const int lseg = tid & 7;
    const uint32_t loff = SWZ(lrow * 128 + lseg * 16);

#define LOAD_STAGE(s, kc) do { \
        int _k0 = ((kc) & 31) * 64; \
        const __half* _Bb = ((kc) >= 32) ? Blo : Bhi; \
        uint32_t _as = sb + (s) * STAGE_B; \
        uint32_t _bs = _as + 16384; \
        const __half* _ap = A + (size_t)(bm + lrow) * Dq + _k0 + lseg * 8; \
        const __half* _bp = _Bb + (size_t)(bn + lrow) * Dq + _k0 + lseg * 8; \
        _Pragma("unroll") \
        for (int _i = 0; _i < 4; _i++) { \
            cp16(_as + loff + _i * 4096, _ap + (size_t)_i * 32 * Dq); \
            cp16(_bs + loff + _i * 4096, _bp + (size_t)_i * 32 * Dq); \
        } \
        asm volatile("cp.async.commit_group;" ::: "memory"); \
    } while (0)

    const int aq = lane >> 3;
    const int am = (lane & 7) + (aq & 1) * 8;
    const int akb = (aq >> 1) * 8;
    const int bl = lane & 15;
    const int bn8 = bl & 7;
    const int bkb = (bl >> 3) * 8;

    LOAD_STAGE(0, 0);
    LOAD_STAGE(1, 1);

    for (int c = 0; c < GNC; c++) {
        if (c == GNC - 1) {
            asm volatile("cp.async.wait_group 0;" ::: "memory");
        } else {
            asm volatile("cp.async.wait_group 1;" ::: "memory");
        }
        __syncthreads();
        if (c + 2 < GNC) LOAD_STAGE((c + 2) % 3, c + 2);

        const uint32_t As = sb + (c % 3) * STAGE_B;
        const uint32_t Bs = As + 16384;
#pragma unroll
        for (int ks = 0; ks < 4; ks++) {
            const int k0 = ks * 16;
            uint32_t af[4][4];
#pragma unroll
            for (int mt = 0; mt < 4; mt++) {
                int m = wm * 64 + mt * 16 + am;
                ldsm_x4(af[mt][0], af[mt][1], af[mt][2], af[mt][3],
                        As + SWZ(m * 128 + (k0 + akb) * 2));
            }
            uint32_t bf[4][2];
#pragma unroll
            for (int nt = 0; nt < 4; nt++) {
                int n = wn * 32 + nt * 8 + bn8;
                ldsm_x2(bf[nt][0], bf[nt][1],
                        Bs + SWZ(n * 128 + (k0 + bkb) * 2));
            }
#pragma unroll
            for (int mt = 0; mt < 4; mt++)
#pragma unroll
                for (int nt = 0; nt < 4; nt++)
                    mma16816(acc[mt][nt], af[mt], bf[nt]);
        }
    }

    const int r0 = bm + wm * 64 + (lane >> 2);
    const int c0 = bn + wn * 32 + (lane & 3) * 2;
#pragma unroll
    for (int mt = 0; mt < 4; mt++) {
#pragma unroll
        for (int nt = 0; nt < 4; nt++) {
            float2* p0 = (float2*)(C + (size_t)(r0 + mt * 16) * ldc + c0 + nt * 8);
            float2* p1 = (float2*)(C + (size_t)(r0 + mt * 16 + 8) * ldc + c0 + nt * 8);
            *p0 = make_float2(acc[mt][nt][0], acc[mt][nt][1]);
            *p1 = make_float2(acc[mt][nt][2], acc[mt][nt][3]);
        }
    }
}

// ---------------- beta / g kernel ----------------
__global__ void betag_kernel(const float* __restrict__ x,
                             const float* __restrict__ Wb,
                             const float* __restrict__ Wa,
                             const float* __restrict__ A_log,
                             const float* __restrict__ dt_bias,
                             float* __restrict__ beta,
                             float* __restrict__ gdec)
{
    const int bl = blockIdx.x;
    const int h = threadIdx.x >> 5;
    const int lane = threadIdx.x & 31;
    const float* xr = x + (size_t)bl * Dq;
    const float* wb = Wb + (size_t)h * Dq;
    const float* wa = Wa + (size_t)h * Dq;
    float sb = 0.f, sa = 0.f;
    for (int i = lane; i < Dq; i += 32) {
        float xv = xr[i];
        sb += xv * wb[i];
        sa += xv * wa[i];
    }
#pragma unroll
    for (int off = 16; off > 0; off >>= 1) {
        sb += __shfl_down_sync(0xffffffffu, sb, off);
        sa += __shfl_down_sync(0xffffffffu, sa, off);
    }
    if (lane == 0) {
        const int b = bl / Lq, l = bl % Lq;
        float bet = 1.f / (1.f + expf(-sb));
        float z = sa + dt_bias[h];
        float sp = (z > 15.f) ? z : log1pf(expf(z));
        float g = -expf(A_log[h]) * sp;
        size_t o = ((size_t)(b * Hq + h)) * Lq + l;
        beta[o] = bet;
        gdec[o] = g;
    }
}

// ---------------- causal dwconv + silu + l2 norm (reads merged proj) ----------
__global__ void conv_kernel(const float* __restrict__ proj,
                            const float* __restrict__ wq, const float* __restrict__ wk,
                            const float* __restrict__ wv,
                            float* __restrict__ oq, float* __restrict__ ok,
                            float* __restrict__ ov)
{
    const int blk = blockIdx.x;
    const int h = blk % Hq;
    const int bl = blk / Hq;
    const int l = bl % Lq;
    const int d = threadIdx.x;
    const int c = h * Dh + d;

    float aq = 0.f, ak = 0.f, av = 0.f;
#pragma unroll
    for (int j = 0; j < KW; j++) {
        int ll = l - (KW - 1) + j;
        if (ll >= 0) {
            size_t idx = ((size_t)(bl - l + ll)) * (4 * Dq) + c;
            aq += wq[c * KW + j] * proj[idx];
            ak += wk[c * KW + j] * proj[idx + Dq];
            av += wv[c * KW + j] * proj[idx + 2 * Dq];
        }
    }
    aq = aq / (1.f + expf(-aq));
    ak = ak / (1.f + expf(-ak));
    av = av / (1.f + expf(-av));

    float sq = aq * aq, sk = ak * ak;
#pragma unroll
    for (int off = 16; off > 0; off >>= 1) {
        sq += __shfl_xor_sync(0xffffffffu, sq, off);
        sk += __shfl_xor_sync(0xffffffffu, sk, off);
    }
    __shared__ float shq[4], shk[4];
    const int wid = threadIdx.x >> 5;
    if ((threadIdx.x & 31) == 0) { shq[wid] = sq; shk[wid] = sk; }
    __syncthreads();
    float sumq = shq[0] + shq[1] + shq[2] + shq[3];
    float sumk = shk[0] + shk[1] + shk[2] + shk[3];
    float invq = 1.f / fmaxf(sqrtf(sumq), 1e-12f);
    float invk = 1.f / fmaxf(sqrtf(sumk), 1e-12f);

    size_t base = (size_t)bl * Dq + c;
    oq[base] = aq * invq * 0.08838834764831845f;
    ok[base] = ak * invk;
    ov[base] = av;
}

// ---------------- chunked gated delta-rule scan (register-tiled) ----------------
#define SKT 132
#define SAT 68
#define SVT 36

#define SK_OFF  0
#define SQ_OFF  8448
#define SS_OFF  16896
#define SA_OFF  21120
#define SV_OFF  25472
#define SP_OFF  27776
#define SC_OFF  30080
#define SCAN_SMEM_FLOATS (SC_OFF + 320)
#define SCAN_SMEM_BYTES (SCAN_SMEM_FLOATS * 4)

__global__ __launch_bounds__(256, 1)
void scan_kernel(const float* __restrict__ q, const float* __restrict__ k,
                 const float* __restrict__ v, const float* __restrict__ beta,
                 const float* __restrict__ gdec, const float* __restrict__ S0,
                 float* __restrict__ o, float* __restrict__ Sout)
{
    extern __shared__ float sm[];
    float* sK = sm + SK_OFF;
    float* sQ = sm + SQ_OFF;
    float* sS = sm + SS_OFF;
    float* sA = sm + SA_OFF;
    float* sV = sm + SV_OFF;
    float* sP = sm + SP_OFF;
    float* slg = sm + SC_OFF;
    float* sgam = slg + 64;
    float* sgCr = sgam + 64;
    float* sbet = sgCr + 64;
    float* sgg = sbet + 64;

    const int bh = blockIdx.x >> 2;
    const int grp = blockIdx.x & 3;
    const int b = bh >> 4;
    const int h = bh & 15;
    const int dv0 = grp * 32;
    const int tid = threadIdx.x;
    const int t_hi = tid >> 4;
    const int t_lo = tid & 15;

    for (int idx = tid; idx < 32 * 128; idx += 256) {
        int dv = idx >> 7, dk = idx & 127;
        sS[dv * SKT + dk] = S0[((size_t)bh * 128 + dv0 + dv) * 128 + dk];
    }

    for (int n = 0; n < Nq; n++) {
        const int l0 = n * Cq;
        for (int idx = tid; idx < 64 * 128; idx += 256) {
            int i = idx >> 7, d = idx & 127;
            size_t gi = (((size_t)(b * Lq + l0 + i)) * Hq + h) * Dh + d;
            sK[i * SKT + d] = k[gi];
            sQ[i * SKT + d] = q[gi];
        }
        for (int idx = tid; idx < 64 * 32; idx += 256) {
            int i = idx >> 5, dv = idx & 31;
            sV[i * SVT + dv] = v[(((size_t)(b * Lq + l0 + i)) * Hq + h) * Dh + dv0 + dv];
        }
        if (tid < 64) {
            sbet[tid] = beta[(size_t)bh * Lq + l0 + tid];
            sgg[tid] = gdec[(size_t)bh * Lq + l0 + tid];
        }
        __syncthreads();
        if (tid == 0) {
            float c = 0.f;
            for (int i = 0; i < 64; i++) { c += sgg[i]; slg[i] = c; }
        }
        __syncthreads();
        const float lgC = slg[63];
        if (tid < 64) {
            sgam[tid] = expf(slg[tid]);
            sgCr[tid] = expf(lgC - slg[tid]);
        }
        __syncthreads();
        const float gammaC = expf(lgC);

        // ---- A = beta_i * exp(lg_i - lg_j) * (K_i . K_j) (strict lower; diag 1) ----
        {
            float acc[4][4];
#pragma unroll
            for (int r = 0; r < 4; r++)
#pragma unroll
                for (int c = 0; c < 4; c++) acc[r][c] = 0.f;
            for (int d = 0; d < 128; d += 4) {
                float4 av[4], bv[4];
#pragma unroll
                for (int r = 0; r < 4; r++)
                    av[r] = *(const float4*)&sK[(t_hi + 16 * r) * SKT + d];
#pragma unroll
                for (int c = 0; c < 4; c++)
                    bv[c] = *(const float4*)&sK[(t_lo + 16 * c) * SKT + d];
#pragma unroll
                for (int r = 0; r < 4; r++)
#pragma unroll
                    for (int c = 0; c < 4; c++) acc[r][c] += dot4(av[r], bv[c]);
            }
#pragma unroll
            for (int r = 0; r < 4; r++) {
                int i = t_hi + 16 * r;
#pragma unroll
                for (int c = 0; c < 4; c++) {
                    int j = t_lo + 16 * c;
                    float val;
                    if (j < i) val = sbet[i] * expf(slg[i] - slg[j]) * acc[r][c];
                    else val = (i == j) ? 1.f : 0.f;
                    sA[i * SAT + j] = val;
                }
            }
        }
        __syncthreads();

        // ---- P = beta_i * (V - gamma_i * K @ S^T) ----
        {
            float acc[4][2];
#pragma unroll
            for (int r = 0; r < 4; r++) { acc[r][0] = 0.f; acc[r][1] = 0.f; }
            for (int d = 0; d < 128; d += 4) {
                float4 av[4], bv[2];
#pragma unroll
                for (int r = 0; r < 4; r++)
                    av[r] = *(const float4*)&sK[(t_hi + 16 * r) * SKT + d];
                bv[0] = *(const float4*)&sS[t_lo * SKT + d];
                bv[1] = *(const float4*)&sS[(t_lo + 16) * SKT + d];
#pragma unroll
                for (int r = 0; r < 4; r++) {
                    acc[r][0] += dot4(av[r], bv[0]);
                    acc[r][1] += dot4(av[r], bv[1]);
                }
            }
#pragma unroll
            for (int r = 0; r < 4; r++) {
                int i = t_hi + 16 * r;
#pragma unroll
                for (int c = 0; c < 2; c++) {
                    int dv = t_lo + 16 * c;
                    sP[i * SVT + dv] = sbet[i] * (sV[i * SVT + dv] - sgam[i] * acc[r][c]);
                }
            }
        }
        __syncthreads();

        // ---- solve A * mid = P in place (blocked forward substitution) ----
#pragma unroll 1
        for (int blk = 0; blk < 8; blk++) {
            const int r0 = blk * 8;
            if (tid < 32) {
                const int dv = tid;
                float vals[8];
                vals[0] = sP[r0 * SVT + dv];
#pragma unroll
                for (int r = 1; r < 8; r++) {
                    float acc = sP[(r0 + r) * SVT + dv];
#pragma unroll
                    for (int m = 0; m < 8; m++)
                        if (m < r) acc -= sA[(r0 + r) * SAT + r0 + m] * vals[m];
                    vals[r] = acc;
                }
#pragma unroll
                for (int r = 1; r < 8; r++) sP[(r0 + r) * SVT + dv] = vals[r];
            }
            __syncthreads();
            const int nrem = 64 - r0 - 8;
            if (nrem > 0) {
                for (int idx = tid; idx < nrem * 32; idx += 256) {
                    int i = r0 + 8 + (idx >> 5);
                    int dv = idx & 31;
                    float acc = sP[i * SVT + dv];
#pragma unroll
                    for (int m = 0; m < 8; m++)
                        acc -= sA[i * SAT + r0 + m] * sP[(r0 + m) * SVT + dv];
                    sP[i * SVT + dv] = acc;
                }
            }
            __syncthreads();
        }

        // ---- attn = (Q@K^T) * exp(lg_i - lg_j), j <= i (overwrite sA) ----
        {
            float acc[4][4];
#pragma unroll
            for (int r = 0; r < 4; r++)
#pragma unroll
                for (int c = 0; c < 4; c++) acc[r][c] = 0.f;
            for (int d = 0; d < 128; d += 4) {
                float4 av[4], bv[4];
#pragma unroll
                for (int r = 0; r < 4; r++)
                    av[r] = *(const float4*)&sQ[(t_hi + 16 * r) * SKT + d];
#pragma unroll
                for (int c = 0; c < 4; c++)
                    bv[c] = *(const float4*)&sK[(t_lo + 16 * c) * SKT + d];
#pragma unroll
                for (int r = 0; r < 4; r++)
#pragma unroll
                    for (int c = 0; c < 4; c++) acc[r][c] += dot4(av[r], bv[c]);
            }
#pragma unroll
            for (int r = 0; r < 4; r++) {
                int i = t_hi + 16 * r;
#pragma unroll
                for (int c = 0; c < 4; c++) {
                    int j = t_lo + 16 * c;
                    float val = (j <= i) ? expf(slg[i] - slg[j]) * acc[r][c] : 0.f;
                    sA[i * SAT + j] = val;
                }
            }
        }
        __syncthreads();

        // ---- O = gamma_i * (Q @ S^T) + attn @ mid ----
        {
            float acc1[4][2], acc2[4][2];
#pragma unroll
            for (int r = 0; r < 4; r++) {
                acc1[r][0] = acc1[r][1] = 0.f;
                acc2[r][0] = acc2[r][1] = 0.f;
            }
            for (int d = 0; d < 128; d += 4) {
                float4 av[4], bv[2];
#pragma unroll
                for (int r = 0; r < 4; r++)
                    av[r] = *(const float4*)&sQ[(t_hi + 16 * r) * SKT + d];
                bv[0] = *(const float4*)&sS[t_lo * SKT + d];
                bv[1] = *(const float4*)&sS[(t_lo + 16) * SKT + d];
#pragma unroll
                for (int r = 0; r < 4; r++) {
                    acc1[r][0] += dot4(av[r], bv[0]);
                    acc1[r][1] += dot4(av[r], bv[1]);
                }
            }
            for (int j = 0; j < 64; j++) {
                float b0 = sP[j * SVT + t_lo];
                float b1 = sP[j * SVT + t_lo + 16];
#pragma unroll
                for (int r = 0; r < 4; r++) {
                    float a = sA[(t_hi + 16 * r) * SAT + j];
                    acc2[r][0] += a * b0;
                    acc2[r][1] += a * b1;
                }
            }
#pragma unroll
            for (int r = 0; r < 4; r++) {
                int i = t_hi + 16 * r;
                float g = sgam[i];
                size_t go = (((size_t)(b * Lq + l0 + i)) * Hq + h) * Dh + dv0;
                o[go + t_lo] = g * acc1[r][0] + acc2[r][0];
                o[go + t_lo + 16] = g * acc1[r][1] + acc2[r][1];
            }
        }
        __syncthreads();

        // ---- S = gammaC * S + (mid_i * gCr_i)^T @ K ----
        {
            const int dkb = t_lo * 8;
            float acc[2][8];
#pragma unroll
            for (int r = 0; r < 2; r++)
#pragma unroll
                for (int c = 0; c < 8; c++) acc[r][c] = 0.f;
            for (int i = 0; i < 64; i++) {
                float gc = sgCr[i];
                float a0 = sP[i * SVT + t_hi] * gc;
                float a1 = sP[i * SVT + t_hi + 16] * gc;
                float4 k0 = *(const float4*)&sK[i * SKT + dkb];
                float4 k1 = *(const float4*)&sK[i * SKT + dkb + 4];
                acc[0][0] += a0 * k0.x; acc[0][1] += a0 * k0.y;
                acc[0][2] += a0 * k0.z; acc[0][3] += a0 * k0.w;
                acc[0][4] += a0 * k1.x; acc[0][5] += a0 * k1.y;
                acc[0][6] += a0 * k1.z; acc[0][7] += a0 * k1.w;
                acc[1][0] += a1 * k0.x; acc[1][1] += a1 * k0.y;
                acc[1][2] += a1 * k0.z; acc[1][3] += a1 * k0.w;
                acc[1][4] += a1 * k1.x; acc[1][5] += a1 * k1.y;
                acc[1][6] += a1 * k1.z; acc[1][7] += a1 * k1.w;
            }
#pragma unroll
            for (int r = 0; r < 2; r++) {
                int dv = t_hi + 16 * r;
#pragma unroll
                for (int c = 0; c < 8; c++) {
                    float* p = &sS[dv * SKT + dkb + c];
                    *p = gammaC * *p + acc[r][c];
                }
            }
        }
        __syncthreads();
    }

    for (int idx = tid; idx < 32 * 128; idx += 256) {
        int dv = idx >> 7, dk = idx & 127;
        Sout[((size_t)bh * 128 + dv0 + dv) * 128 + dk] = sS[dv * SKT + dk];
    }
}

// ---------------- RMSNorm + gate (silu) -> fp16 directly ----------------
__global__ void gate_kernel(const float* __restrict__ o, const float* __restrict__ proj,
                            const float* __restrict__ norm_w,
                            __half* __restrict__ oh)
{
    const size_t base = (size_t)blockIdx.x * Dh + threadIdx.x;
    const size_t row = blockIdx.x >> 4;
    const size_t inner = (size_t)(blockIdx.x & 15) * Dh + threadIdx.x;
    float ov = o[base];
    float s = ov * ov;
#pragma unroll
    for (int off = 16; off > 0; off >>= 1) s += __shfl_xor_sync(0xffffffffu, s, off);
    __shared__ float sh[4];
    const int wid = threadIdx.x >> 5;
    if ((threadIdx.x & 31) == 0) sh[wid] = s;
    __syncthreads();
    float mean = (sh[0] + sh[1] + sh[2] + sh[3]) * (1.f / 128.f);
    float rs = rsqrtf(mean + EPSq);
    float gv = proj[row * (4 * Dq) + 3 * Dq + inner];
    float sig = gv / (1.f + expf(-gv));
    float val = ov * rs * norm_w[threadIdx.x] * sig;
    oh[base] = __float2half_rn(val);
}

// ---------------- launch ----------------
extern "C" void kernel_launch(void* const* d_in, const int* in_sizes, int n_in,
                              void* d_out, int out_size)
{
    const float* x = (const float*)d_in[0];
    const float* Wq = (const float*)d_in[1];
    const float* Wk = (const float*)d_in[2];
    const float* Wv = (const float*)d_in[3];
    const float* Wb = (const float*)d_in[4];
    const float* Wa = (const float*)d_in[5];
    const float* A_log = (const float*)d_in[6];
    const float* dt_bias = (const float*)d_in[7];
    const float* conv_q = (const float*)d_in[8];
    const float* conv_k = (const float*)d_in[9];
    const float* conv_v = (const float*)d_in[10];
    const float* Wg = (const float*)d_in[11];
    const float* norm_w = (const float*)d_in[12];
    const float* Wo = (const float*)d_in[13];
    const float* S0 = (const float*)d_in[14];

    float* out = (float*)d_out;
    float* Sout = out + (size_t)BLD;

    float *proj, *obuf, *qn, *kn, *vn, *beta, *gdec;
    __half *xh, *whi, *wlo;
    cudaGetSymbolAddress((void**)&proj, g_proj);
    cudaGetSymbolAddress((void**)&obuf, g_obuf);
    cudaGetSymbolAddress((void**)&qn, g_qn);
    cudaGetSymbolAddress((void**)&kn, g_kn);
    cudaGetSymbolAddress((void**)&vn, g_vn);
    cudaGetSymbolAddress((void**)&beta, g_beta);
    cudaGetSymbolAddress((void**)&gdec, g_gdec);
    cudaGetSymbolAddress((void**)&xh, g_xh);
    cudaGetSymbolAddress((void**)&whi, g_whi);
    cudaGetSymbolAddress((void**)&wlo, g_wlo);

    cudaFuncSetAttribute(scan_kernel, cudaFuncAttributeMaxDynamicSharedMemorySize,
                         SCAN_SMEM_BYTES);
    cudaFuncSetAttribute(hmma_gemm, cudaFuncAttributeMaxDynamicSharedMemorySize,
                         GEMM_SMEM_BYTES);

    const size_t WSZ = (size_t)Dq * Dq;

    // splits
    cast_f16<<<BLD / 256, 256>>>(x, xh);
    split2_f16<<<WSZ / 256, 256>>>(Wq, whi, wlo);
    split2_f16<<<WSZ / 256, 256>>>(Wk, whi + WSZ, wlo + WSZ);
    split2_f16<<<WSZ / 256, 256>>>(Wv, whi + 2 * WSZ, wlo + 2 * WSZ);
    split2_f16<<<WSZ / 256, 256>>>(Wg, whi + 3 * WSZ, wlo + 3 * WSZ);

    // merged projection GEMM: [8192, 2048] x [8192, 2048]^T -> [8192, 8192]
    dim3 pgrid(4 * Dq / 128, BLq / 128);   // (64, 64)
    hmma_gemm<<<pgrid, 256, GEMM_SMEM_BYTES>>>(xh, whi, wlo, proj, 4 * Dq);

    split2_f16<<<WSZ / 256, 256>>>(Wo, whi + 4 * WSZ, wlo + 4 * WSZ);
    betag_kernel<<<BLq, 512>>>(x, Wb, Wa, A_log, dt_bias, beta, gdec);

    conv_kernel<<<BLq * Hq, 128>>>(proj, conv_q, conv_k, conv_v, qn, kn, vn);

    scan_kernel<<<Bq * Hq * 4, 256, SCAN_SMEM_BYTES>>>(qn, kn, vn, beta, gdec, S0,
                                                       obuf, Sout);

    gate_kernel<<<BLq * Hq, 128>>>(obuf, proj, norm_w, xh);

    // output projection
    dim3 ogrid(Dq / 128, BLq / 128);       // (16, 64)
    hmma_gemm<<<ogrid, 256, GEMM_SMEM_BYTES>>>(xh, whi + 4 * WSZ, wlo + 4 * WSZ,
                                               out, Dq);
}